// round 12
// baseline (speedup 1.0000x reference)
#include <cuda_runtime.h>
#include <cuda_fp16.h>
#include <math.h>
#include <stdint.h>

#define BN_EPS 1e-3f
#define SLOPE  0.1f
#define CT     30.0f

// ============================ scratch globals ============================
__device__ __half g_h1[256 * 32 * 32 * 128];  // conv1 out NHWC fp16
__device__ __half g_h2[256 * 16 * 16 * 256];  // conv2 out NHWC fp16
__device__ float g_data[256 * 4096];
__device__ float g_G[256 * 256];
__device__ float g_D0[256 * 16];
__device__ __half g_B1[128 * 64];
__device__ __half g_B2[256 * 1152];           // k = kk*128 + ic
__device__ __half g_B3[64 * 2304];            // k = kk*256 + ic

__device__ __forceinline__ uint32_t smem_u32(const void* p) {
    uint32_t a;
    asm("{ .reg .u64 t; cvta.to.shared.u64 t, %1; cvt.u32.u64 %0, t; }" : "=r"(a) : "l"(p));
    return a;
}
__device__ __forceinline__ void cp_async16(uint32_t dst, const void* src) {
    asm volatile("cp.async.cg.shared.global [%0], [%1], 16;" :: "r"(dst), "l"(src));
}
__device__ __forceinline__ void cp_async16z(uint32_t dst, const void* src, int szbytes) {
    asm volatile("cp.async.cg.shared.global [%0], [%1], 16, %2;"
                 :: "r"(dst), "l"(src), "r"(szbytes));
}
__device__ __forceinline__ void ldsm_x4(uint32_t* f, uint32_t addr) {
    asm volatile("ldmatrix.sync.aligned.m8n8.x4.shared.b16 {%0,%1,%2,%3}, [%4];"
                 : "=r"(f[0]), "=r"(f[1]), "=r"(f[2]), "=r"(f[3]) : "r"(addr));
}
__device__ __forceinline__ void mma_f16(float* d, const uint32_t* a, const uint32_t* b) {
    asm volatile(
        "mma.sync.aligned.m16n8k16.row.col.f32.f16.f16.f32 "
        "{%0,%1,%2,%3}, {%4,%5,%6,%7}, {%8,%9}, {%0,%1,%2,%3};"
        : "+f"(d[0]), "+f"(d[1]), "+f"(d[2]), "+f"(d[3])
        : "r"(a[0]), "r"(a[1]), "r"(a[2]), "r"(a[3]), "r"(b[0]), "r"(b[1]));
}

// ============================ weight prep ============================
__global__ __launch_bounds__(128) void prep_w1(const float* __restrict__ w, __half* __restrict__ o)
{
    int oc = threadIdx.x;
    __half* row = o + oc * 64;
#pragma unroll
    for (int j = 0; j < 64; j++) row[j] = __ushort_as_half((unsigned short)0);
#pragma unroll
    for (int j = 0; j < 27; j++) row[j] = __float2half_rn(w[oc * 27 + j]);
}
__global__ __launch_bounds__(256) void prep_w2(const float* __restrict__ w, __half* __restrict__ o)
{
    int oc = blockIdx.x;
    for (int k = threadIdx.x; k < 1152; k += 256) {
        int kk = k >> 7, ic = k & 127;
        o[oc * 1152 + k] = __float2half_rn(w[oc * 1152 + ic * 9 + kk]);
    }
}
__global__ __launch_bounds__(256) void prep_w3(const float* __restrict__ w, __half* __restrict__ o)
{
    int oc = blockIdx.x;
    for (int k = threadIdx.x; k < 2304; k += 256) {
        int kk = k >> 8, ic = k & 255;
        o[oc * 2304 + k] = __float2half_rn(w[oc * 2304 + ic * 9 + kk]);
    }
}

// ============================ conv1: fully fused (x fp32 -> h1 NHWC fp16) ============================
// grid(2048): block handles 128 consecutive output positions of one image (1/8 image).
// smem: x slice fp32 [3][10][64] @0 (7680B), A fp16 tile @7680 (128x144B), B @26112 (128x144B).
// epilogue stage (float, P=129) reuses smem from 0 (66048B total dynamic).
__global__ __launch_bounds__(256)
void conv1_kernel(const float* __restrict__ x, const __half* __restrict__ Bw,
                  const float* __restrict__ bias, const float* __restrict__ g,
                  const float* __restrict__ beta, const float* __restrict__ m,
                  const float* __restrict__ v, __half* __restrict__ out)
{
    extern __shared__ __align__(16) char smem[];
    __shared__ float scs[128], shs[128];
    float* in_s = (float*)smem;                 // 1920 floats
    const int A_OFF = 7680, B_OFF = 26112;

    int tid = threadIdx.x, wid = tid >> 5, lane = tid & 31;
    int wm = wid & 3, wn = wid >> 2;
    int rowbase = blockIdx.x * 128;
    int img = rowbase >> 10, p0 = rowbase & 1023;
    int oh0 = p0 >> 5;
    int ihb0 = 2 * oh0 - 1;

    if (tid < 128) {
        float sc = g[tid] / sqrtf(v[tid] + BN_EPS);
        scs[tid] = sc;
        shs[tid] = beta[tid] - m[tid] * sc + bias[tid] * sc;
    }

    uint32_t sb = smem_u32(smem);

    // B: 128 rows x 128B via cp.async (4 per thread)
#pragma unroll
    for (int i = 0; i < 4; i++) {
        int gi = tid + 256 * i; int rr = gi >> 3, gc = gi & 7;
        cp_async16(sb + B_OFF + rr * 144 + gc * 16, (const char*)Bw + (rr * 64 + gc * 8) * 2);
    }
    asm volatile("cp.async.commit_group;");

    // x slice: [3][10][64] fp32, rows ihb0..ihb0+9 (zero out-of-range)
    const float* xim = x + (size_t)img * 12288;
    for (int i = tid; i < 1920; i += 256) {
        int ic = i / 640, rem = i - ic * 640;
        int r = rem >> 6, cidx = rem & 63;
        int gih = ihb0 + r;
        in_s[i] = (gih >= 0 && gih < 64) ? xim[ic * 4096 + (gih << 6) + cidx] : 0.f;
    }
    __syncthreads();

    // build A tile: thread t<128 -> row t (64 halves = 32 u32), zero-padded j>=27
    if (tid < 128) {
        int p = p0 + tid;
        int oh = p >> 5, ow = p & 31;
        int ohl = oh - oh0;
        uint32_t t[32];
#pragma unroll
        for (int i = 0; i < 32; i++) t[i] = 0;
#pragma unroll
        for (int j = 0; j < 27; j++) {
            int ic = j / 9, kk = j % 9, kh = kk / 3, kw = kk % 3;
            int lih = 2 * ohl + kh;
            int iw = 2 * ow - 1 + kw;
            float val = ((unsigned)iw < 64u) ? in_s[ic * 640 + (lih << 6) + iw] : 0.f;
            t[j >> 1] |= (uint32_t)__half_as_ushort(__float2half_rn(val)) << ((j & 1) * 16);
        }
        uint32_t* arow = (uint32_t*)(smem + A_OFF + tid * 144);
#pragma unroll
        for (int i = 0; i < 32; i++) arow[i] = t[i];
    }
    asm volatile("cp.async.wait_group 0;");
    __syncthreads();

    // single-chunk MMA: BN=128, WN=64, NT=8
    float acc[2][8][4];
#pragma unroll
    for (int i = 0; i < 2; i++)
#pragma unroll
        for (int j = 0; j < 8; j++)
#pragma unroll
            for (int q = 0; q < 4; q++) acc[i][j][q] = 0.f;

    uint32_t ab = sb + A_OFF, bb = sb + B_OFF;
#pragma unroll
    for (int ks = 0; ks < 4; ks++) {
        uint32_t af[2][4];
#pragma unroll
        for (int mt = 0; mt < 2; mt++) {
            uint32_t addr = ab + (wm * 32 + mt * 16 + (lane & 15)) * 144
                            + ks * 32 + ((lane >> 4) << 4);
            ldsm_x4(af[mt], addr);
        }
#pragma unroll
        for (int nt2 = 0; nt2 < 4; nt2++) {
            uint32_t bf[4];
            uint32_t addr = bb + (wn * 64 + nt2 * 16 + (lane & 7) + (((lane >> 4) & 1) << 3)) * 144
                            + ks * 32 + (((lane >> 3) & 1) << 4);
            ldsm_x4(bf, addr);
#pragma unroll
            for (int mt = 0; mt < 2; mt++) {
                mma_f16(acc[mt][2 * nt2],     af[mt], bf);
                mma_f16(acc[mt][2 * nt2 + 1], af[mt], bf + 2);
            }
        }
    }
    __syncthreads();

    // epilogue: stage fp32 (P=129), NHWC half2 stores
    float* stage = (float*)smem;
#pragma unroll
    for (int mt = 0; mt < 2; mt++)
#pragma unroll
        for (int nt = 0; nt < 8; nt++) {
            int r0 = wm * 32 + mt * 16 + (lane >> 2);
            int c0 = wn * 64 + nt * 8 + 2 * (lane & 3);
            stage[r0 * 129 + c0]           = acc[mt][nt][0];
            stage[r0 * 129 + c0 + 1]       = acc[mt][nt][1];
            stage[(r0 + 8) * 129 + c0]     = acc[mt][nt][2];
            stage[(r0 + 8) * 129 + c0 + 1] = acc[mt][nt][3];
        }
    __syncthreads();

    __half2* o2 = (__half2*)out;
#pragma unroll
    for (int rblk = 0; rblk < 16; rblk++) {
        int r = wid * 16 + rblk;
        size_t base2 = ((size_t)(rowbase + r) * 128) >> 1;
#pragma unroll
        for (int cc = lane; cc < 64; cc += 32) {
            float y0 = stage[r * 129 + 2 * cc] * scs[2 * cc] + shs[2 * cc];
            float y1 = stage[r * 129 + 2 * cc + 1] * scs[2 * cc + 1] + shs[2 * cc + 1];
            y0 = y0 > 0.f ? y0 : SLOPE * y0;
            y1 = y1 > 0.f ? y1 : SLOPE * y1;
            o2[base2 + cc] = __floats2half2_rn(y0, y1);
        }
    }
}

// ============================ HMMA GEMM (fp16, fused gather; CONV 2/3) ============================
template<int CONV>
__global__ __launch_bounds__(256)
void gemm_kernel(const __half* __restrict__ A, const __half* __restrict__ Bw,
                 const float* __restrict__ bias, const float* __restrict__ g,
                 const float* __restrict__ beta, const float* __restrict__ m,
                 const float* __restrict__ v, void* __restrict__ out_v)
{
    constexpr int N  = (CONV == 2) ? 256 : 64;
    constexpr int KS = (CONV == 2) ? 1152 : 2304;
    constexpr int NC = KS / 64;
    constexpr int BN = N;
    constexpr int WN = BN / 2;
    constexpr int NT = WN / 8;
    constexpr int ABUF = 128 * 144;
    constexpr int BBUF = BN * 144;
    constexpr int BGI = (BN * 8) / 256;
    constexpr int P = BN + 1;

    extern __shared__ __align__(16) char smem[];
    __shared__ float scs[256], shs[256];

    int tid = threadIdx.x, wid = tid >> 5, lane = tid & 31;
    int wm = wid & 3, wn = wid >> 2;
    int rowbase = blockIdx.x * 128;
    int img0 = rowbase >> 8, p0 = rowbase & 255;

    if (tid < N) {
        float sc = g[tid] / sqrtf(v[tid] + BN_EPS);
        scs[tid] = sc;
        shs[tid] = beta[tid] - m[tid] * sc + bias[tid] * sc;
    }

    uint32_t sb = smem_u32(smem);

    float acc[2][NT][4];
#pragma unroll
    for (int i = 0; i < 2; i++)
#pragma unroll
        for (int j = 0; j < NT; j++)
#pragma unroll
            for (int q = 0; q < 4; q++) acc[i][j][q] = 0.f;

    auto issue_copy = [&](int c) {
        int buf = c & 1;
        uint32_t ab = sb + buf * (ABUF + BBUF);
        uint32_t bb = ab + ABUF;
        if (CONV == 2) {
            int kk = c >> 1, icg = c & 1;
            int kh = kk / 3, kw = kk - 3 * kh;
#pragma unroll
            for (int i = 0; i < 4; i++) {
                int gi = tid + 256 * i; int rr = gi >> 3, gc = gi & 7;
                int p = p0 + rr;
                int oh = p >> 4, ow = p & 15;
                int ih = 2 * oh - 1 + kh, iw = 2 * ow - 1 + kw;
                bool ok = ((unsigned)ih < 32u) && ((unsigned)iw < 32u);
                size_t off = (((size_t)img0 * 32 + (ok ? ih : 0)) * 32 + (ok ? iw : 0)) * 128
                             + icg * 64 + gc * 8;
                cp_async16z(ab + rr * 144 + gc * 16, (const char*)A + off * 2, ok ? 16 : 0);
            }
        } else {
            int kk = c >> 2, icg = c & 3;
            int kh = kk / 3, kw = kk - 3 * kh;
#pragma unroll
            for (int i = 0; i < 4; i++) {
                int gi = tid + 256 * i; int rr = gi >> 3, gc = gi & 7;
                int grow = rowbase + rr;
                int img = grow >> 6, p = grow & 63;
                int oh = p >> 3, ow = p & 7;
                int ih = 2 * oh - 1 + kh, iw = 2 * ow - 1 + kw;
                bool ok = ((unsigned)ih < 16u) && ((unsigned)iw < 16u);
                size_t off = (((size_t)img * 16 + (ok ? ih : 0)) * 16 + (ok ? iw : 0)) * 256
                             + icg * 64 + gc * 8;
                cp_async16z(ab + rr * 144 + gc * 16, (const char*)A + off * 2, ok ? 16 : 0);
            }
        }
#pragma unroll
        for (int i = 0; i < BGI; i++) {
            int gi = tid + 256 * i; int rr = gi >> 3, gc = gi & 7;
            cp_async16(bb + rr * 144 + gc * 16,
                       (const char*)Bw + ((size_t)rr * KS + c * 64) * 2 + gc * 16);
        }
        asm volatile("cp.async.commit_group;");
    };

    issue_copy(0);
    for (int c = 0; c < NC; c++) {
        if (c + 1 < NC) {
            issue_copy(c + 1);
            asm volatile("cp.async.wait_group 1;");
        } else {
            asm volatile("cp.async.wait_group 0;");
        }
        __syncthreads();

        int buf = c & 1;
        uint32_t ab = sb + buf * (ABUF + BBUF);
        uint32_t bb = ab + ABUF;
#pragma unroll
        for (int ks = 0; ks < 4; ks++) {
            uint32_t af[2][4];
#pragma unroll
            for (int mt = 0; mt < 2; mt++) {
                uint32_t addr = ab + (wm * 32 + mt * 16 + (lane & 15)) * 144
                                + ks * 32 + ((lane >> 4) << 4);
                ldsm_x4(af[mt], addr);
            }
#pragma unroll
            for (int nt2 = 0; nt2 < NT / 2; nt2++) {
                uint32_t bf[4];
                uint32_t addr = bb + (wn * WN + nt2 * 16 + (lane & 7) + (((lane >> 4) & 1) << 3)) * 144
                                + ks * 32 + (((lane >> 3) & 1) << 4);
                ldsm_x4(bf, addr);
#pragma unroll
                for (int mt = 0; mt < 2; mt++) {
                    mma_f16(acc[mt][2 * nt2],     af[mt], bf);
                    mma_f16(acc[mt][2 * nt2 + 1], af[mt], bf + 2);
                }
            }
        }
        __syncthreads();
    }

    if (CONV == 3) {
        float* stage = (float*)smem;
#pragma unroll
        for (int mt = 0; mt < 2; mt++)
#pragma unroll
            for (int nt = 0; nt < NT; nt++) {
                int r0 = wm * 32 + mt * 16 + (lane >> 2);
                int c0 = wn * WN + nt * 8 + 2 * (lane & 3);
                stage[r0 * P + c0]           = acc[mt][nt][0];
                stage[r0 * P + c0 + 1]       = acc[mt][nt][1];
                stage[(r0 + 8) * P + c0]     = acc[mt][nt][2];
                stage[(r0 + 8) * P + c0 + 1] = acc[mt][nt][3];
            }
        __syncthreads();
#pragma unroll
        for (int j = 0; j < BN / 8; j++) {
            int colL = wid * (BN / 8) + j;
            float sc = scs[colL], sh = shs[colL];
#pragma unroll
            for (int it = 0; it < 4; it++) {
                int r = it * 32 + lane;
                float y = stage[r * P + colL] * sc + sh;
                y = y > 0.f ? y : SLOPE * y;
                int grow = rowbase + r;
                int img = grow >> 6, p = grow & 63;
                ((float*)out_v)[(size_t)img * 4096 + colL * 64 + p] = y;
            }
        }
    } else {
        // two-half epilogue (stage P2=129) so smem stays at loop size -> 2 CTAs/SM
        float* stage = (float*)smem;
        __half2* o2 = (__half2*)out_v;
#pragma unroll
        for (int h = 0; h < 2; h++) {
            __syncthreads();
            if (wn == h) {
#pragma unroll
                for (int mt = 0; mt < 2; mt++)
#pragma unroll
                    for (int nt = 0; nt < NT; nt++) {
                        int r0 = wm * 32 + mt * 16 + (lane >> 2);
                        int c0 = nt * 8 + 2 * (lane & 3);
                        stage[r0 * 129 + c0]           = acc[mt][nt][0];
                        stage[r0 * 129 + c0 + 1]       = acc[mt][nt][1];
                        stage[(r0 + 8) * 129 + c0]     = acc[mt][nt][2];
                        stage[(r0 + 8) * 129 + c0 + 1] = acc[mt][nt][3];
                    }
            }
            __syncthreads();
#pragma unroll
            for (int rblk = 0; rblk < 16; rblk++) {
                int r = wid * 16 + rblk;
                size_t base2 = ((size_t)(rowbase + r) * 256 + h * 128) >> 1;
#pragma unroll
                for (int cc = lane; cc < 64; cc += 32) {
                    int gc = h * 128 + 2 * cc;
                    float y0 = stage[r * 129 + 2 * cc] * scs[gc] + shs[gc];
                    float y1 = stage[r * 129 + 2 * cc + 1] * scs[gc + 1] + shs[gc + 1];
                    y0 = y0 > 0.f ? y0 : SLOPE * y0;
                    y1 = y1 > 0.f ? y1 : SLOPE * y1;
                    o2[base2 + cc] = __floats2half2_rn(y0, y1);
                }
            }
        }
    }
}

// ============================ k-means ============================
__global__ __launch_bounds__(256) void normalize_kernel(float* __restrict__ data)
{
    int row = blockIdx.x, tid = threadIdx.x;
    float* dr = data + row * 4096;
    float vals[16];
    float s = 0.f;
#pragma unroll
    for (int i = 0; i < 16; i++) { vals[i] = dr[tid + i * 256]; s = fmaf(vals[i], vals[i], s); }
    __shared__ float sm[9];
    int lane = tid & 31, warp = tid >> 5;
#pragma unroll
    for (int off = 16; off > 0; off >>= 1) s += __shfl_down_sync(0xffffffffu, s, off);
    if (lane == 0) sm[warp] = s;
    __syncthreads();
    if (tid == 0) {
        float t = 0.f;
        for (int w = 0; w < 8; w++) t += sm[w];
        sm[8] = 1.f / sqrtf(t);
    }
    __syncthreads();
    float inv = sm[8];
#pragma unroll
    for (int i = 0; i < 16; i++) dr[tid + i * 256] = vals[i] * inv;
}

__global__ __launch_bounds__(256) void gram_kernel(const float* __restrict__ data, float* __restrict__ G)
{
    __shared__ float at[16][129];
    __shared__ float bt[16][129];
    int tid = threadIdx.x;
    int ty = tid >> 4, tx = tid & 15;
    int r0 = blockIdx.y * 16, c0 = blockIdx.x * 16;
    float acc = 0.f;
    for (int kc = 0; kc < 4096; kc += 128) {
        __syncthreads();
        for (int i = tid; i < 2048; i += 256) {
            int rr = i >> 7, cc = i & 127;
            at[rr][cc] = data[(size_t)(r0 + rr) * 4096 + kc + cc];
            bt[rr][cc] = data[(size_t)(c0 + rr) * 4096 + kc + cc];
        }
        __syncthreads();
#pragma unroll 16
        for (int k = 0; k < 128; k++) acc = fmaf(at[ty][k], bt[tx][k], acc);
    }
    G[(r0 + ty) * 256 + c0 + tx] = acc;
}

__global__ __launch_bounds__(256) void dist0_kernel(
    const float* __restrict__ data, const float* __restrict__ mu, float* __restrict__ dout)
{
    int row = blockIdx.x, tid = threadIdx.x;
    const float* dr = data + row * 4096;
    float acc[16];
#pragma unroll
    for (int k = 0; k < 16; k++) acc[k] = 0.f;
#pragma unroll 4
    for (int i = 0; i < 16; i++) {
        int j = tid + i * 256;
        float dj = __ldg(dr + j);
#pragma unroll
        for (int k = 0; k < 16; k++) acc[k] = fmaf(dj, __ldg(mu + k * 4096 + j), acc[k]);
    }
    __shared__ float wsum[8][16];
    int lane = tid & 31, warp = tid >> 5;
#pragma unroll
    for (int k = 0; k < 16; k++) {
        float vv = acc[k];
#pragma unroll
        for (int off = 16; off > 0; off >>= 1) vv += __shfl_down_sync(0xffffffffu, vv, off);
        if (lane == 0) wsum[warp][k] = vv;
    }
    __syncthreads();
    if (tid < 16) {
        float s = 0.f;
#pragma unroll
        for (int w = 0; w < 8; w++) s += wsum[w][tid];
        dout[row * 16 + tid] = s;
    }
}

__global__ __launch_bounds__(1024) void kmeans_iter_kernel(
    const float* __restrict__ G, const float* __restrict__ D0, float* __restrict__ out)
{
    __shared__ float rD[256 * 16];
    __shared__ float part[32][16];
    __shared__ float invcs[16];
    int tid = threadIdx.x;
    int row = tid >> 2, kg = tid & 3;

    for (int it = 0; it < 12; it++) {
        float L[4];
        if (it == 0) {
#pragma unroll
            for (int i = 0; i < 4; i++) L[i] = CT * D0[row * 16 + kg * 4 + i];
        } else {
            float a0 = 0.f, a1 = 0.f, a2 = 0.f, a3 = 0.f;
            const float4* gr = (const float4*)(G + (size_t)row * 256);
            const float4* rp = (const float4*)&rD[kg * 4];
#pragma unroll 8
            for (int n4 = 0; n4 < 64; n4++) {
                float4 gv = __ldg(gr + n4);
                float4 r0 = rp[n4 * 16];
                float4 r1 = rp[n4 * 16 + 4];
                float4 r2 = rp[n4 * 16 + 8];
                float4 r3 = rp[n4 * 16 + 12];
                a0 += gv.x * r0.x + gv.y * r1.x + gv.z * r2.x + gv.w * r3.x;
                a1 += gv.x * r0.y + gv.y * r1.y + gv.z * r2.y + gv.w * r3.y;
                a2 += gv.x * r0.z + gv.y * r1.z + gv.z * r2.z + gv.w * r3.z;
                a3 += gv.x * r0.w + gv.y * r1.w + gv.z * r2.w + gv.w * r3.w;
            }
            L[0] = CT * a0; L[1] = CT * a1; L[2] = CT * a2; L[3] = CT * a3;
        }
        float mx = fmaxf(fmaxf(L[0], L[1]), fmaxf(L[2], L[3]));
        mx = fmaxf(mx, __shfl_xor_sync(0xffffffffu, mx, 1));
        mx = fmaxf(mx, __shfl_xor_sync(0xffffffffu, mx, 2));
        float e[4]; float s = 0.f;
#pragma unroll
        for (int i = 0; i < 4; i++) { e[i] = expf(L[i] - mx); s += e[i]; }
        s += __shfl_xor_sync(0xffffffffu, s, 1);
        s += __shfl_xor_sync(0xffffffffu, s, 2);
        float inv = 1.f / s;
#pragma unroll
        for (int i = 0; i < 4; i++) e[i] *= inv;

        if (it == 11) {
            *(float4*)&out[row * 16 + kg * 4] = make_float4(e[0], e[1], e[2], e[3]);
            return;
        }
        __syncthreads();
        *(float4*)&rD[row * 16 + kg * 4] = make_float4(e[0], e[1], e[2], e[3]);
        __syncthreads();
        if (tid < 512) {
            int k = tid & 15, grp = tid >> 4;
            float ss = 0.f;
#pragma unroll
            for (int n = 0; n < 8; n++) ss += rD[(grp * 8 + n) * 16 + k];
            part[grp][k] = ss;
        }
        __syncthreads();
        if (tid < 16) {
            float ss = 0.f;
#pragma unroll
            for (int gq = 0; gq < 32; gq++) ss += part[gq][tid];
            invcs[tid] = 1.f / ss;
        }
        __syncthreads();
#pragma unroll
        for (int i = 0; i < 4; i++)
            rD[row * 16 + kg * 4 + i] = e[i] * invcs[kg * 4 + i];
        __syncthreads();
    }
}

// ============================ host ============================
extern "C" void kernel_launch(void* const* d_in, const int* in_sizes, int n_in,
                              void* d_out, int out_size)
{
    const float* x   = (const float*)d_in[0];
    const float* w1  = (const float*)d_in[1];
    const float* b1  = (const float*)d_in[2];
    const float* g1  = (const float*)d_in[3];
    const float* be1 = (const float*)d_in[4];
    const float* m1  = (const float*)d_in[5];
    const float* v1  = (const float*)d_in[6];
    const float* w2  = (const float*)d_in[7];
    const float* b2  = (const float*)d_in[8];
    const float* g2  = (const float*)d_in[9];
    const float* be2 = (const float*)d_in[10];
    const float* m2  = (const float*)d_in[11];
    const float* v2  = (const float*)d_in[12];
    const float* w3  = (const float*)d_in[13];
    const float* b3  = (const float*)d_in[14];
    const float* g3  = (const float*)d_in[15];
    const float* be3 = (const float*)d_in[16];
    const float* m3  = (const float*)d_in[17];
    const float* v3  = (const float*)d_in[18];
    const float* mu0 = (const float*)d_in[19];

    float *data, *G, *D0;
    __half *h1, *h2, *B1, *B2, *B3;
    cudaGetSymbolAddress((void**)&h1, g_h1);
    cudaGetSymbolAddress((void**)&h2, g_h2);
    cudaGetSymbolAddress((void**)&data, g_data);
    cudaGetSymbolAddress((void**)&G, g_G);
    cudaGetSymbolAddress((void**)&D0, g_D0);
    cudaGetSymbolAddress((void**)&B1, g_B1);
    cudaGetSymbolAddress((void**)&B2, g_B2);
    cudaGetSymbolAddress((void**)&B3, g_B3);

    const int smem_c1 = 66048;                         // stage dominates
    const int smem_g2 = 2 * (128 * 144 + 256 * 144);   // 110592 (two-half stage fits)
    const int smem_g3 = 2 * (128 * 144 + 64 * 144);    // 55296
    cudaFuncSetAttribute(conv1_kernel, cudaFuncAttributeMaxDynamicSharedMemorySize, smem_c1);
    cudaFuncSetAttribute(gemm_kernel<2>, cudaFuncAttributeMaxDynamicSharedMemorySize, smem_g2);
    cudaFuncSetAttribute(gemm_kernel<3>, cudaFuncAttributeMaxDynamicSharedMemorySize, smem_g3);

    prep_w1<<<1, 128>>>(w1, B1);
    prep_w2<<<256, 256>>>(w2, B2);
    prep_w3<<<64, 256>>>(w3, B3);

    conv1_kernel<<<2048, 256, smem_c1>>>(x, B1, b1, g1, be1, m1, v1, h1);
    gemm_kernel<2><<<dim3(512, 1), 256, smem_g2>>>(h1, B2, b2, g2, be2, m2, v2, h2);
    gemm_kernel<3><<<dim3(128, 1), 256, smem_g3>>>(h2, B3, b3, g3, be3, m3, v3, data);

    normalize_kernel<<<256, 256>>>(data);
    gram_kernel<<<dim3(16, 16), 256>>>(data, G);
    dist0_kernel<<<256, 256>>>(data, mu0, D0);
    kmeans_iter_kernel<<<1, 1024>>>(G, D0, (float*)d_out);
}

// round 13
// speedup vs baseline: 1.2961x; 1.2961x over previous
#include <cuda_runtime.h>
#include <cuda_fp16.h>
#include <math.h>
#include <stdint.h>

#define BN_EPS 1e-3f
#define SLOPE  0.1f
#define CT     30.0f

// ============================ scratch globals ============================
__device__ __half g_h1[256 * 32 * 32 * 128];  // conv1 out NHWC fp16
__device__ __half g_h2[256 * 16 * 16 * 256];  // conv2 out NHWC fp16
__device__ float g_data[256 * 4096];
__device__ float g_G[256 * 256];
__device__ float g_D0[256 * 16];
__device__ float g_Ra[256 * 16];
__device__ float g_Rb[256 * 16];
__device__ float g_PSa[16 * 16];
__device__ float g_PSb[16 * 16];
__device__ __half g_B1[128 * 64];
__device__ __half g_B2[256 * 1152];           // k = kk*128 + ic
__device__ __half g_B3[64 * 2304];            // k = kk*256 + ic

__device__ __forceinline__ uint32_t smem_u32(const void* p) {
    uint32_t a;
    asm("{ .reg .u64 t; cvta.to.shared.u64 t, %1; cvt.u32.u64 %0, t; }" : "=r"(a) : "l"(p));
    return a;
}
__device__ __forceinline__ void cp_async16(uint32_t dst, const void* src) {
    asm volatile("cp.async.cg.shared.global [%0], [%1], 16;" :: "r"(dst), "l"(src));
}
__device__ __forceinline__ void cp_async16z(uint32_t dst, const void* src, int szbytes) {
    asm volatile("cp.async.cg.shared.global [%0], [%1], 16, %2;"
                 :: "r"(dst), "l"(src), "r"(szbytes));
}
__device__ __forceinline__ void ldsm_x4(uint32_t* f, uint32_t addr) {
    asm volatile("ldmatrix.sync.aligned.m8n8.x4.shared.b16 {%0,%1,%2,%3}, [%4];"
                 : "=r"(f[0]), "=r"(f[1]), "=r"(f[2]), "=r"(f[3]) : "r"(addr));
}
__device__ __forceinline__ void mma_f16(float* d, const uint32_t* a, const uint32_t* b) {
    asm volatile(
        "mma.sync.aligned.m16n8k16.row.col.f32.f16.f16.f32 "
        "{%0,%1,%2,%3}, {%4,%5,%6,%7}, {%8,%9}, {%0,%1,%2,%3};"
        : "+f"(d[0]), "+f"(d[1]), "+f"(d[2]), "+f"(d[3])
        : "r"(a[0]), "r"(a[1]), "r"(a[2]), "r"(a[3]), "r"(b[0]), "r"(b[1]));
}

// ============================ weight prep ============================
__global__ __launch_bounds__(128) void prep_w1(const float* __restrict__ w, __half* __restrict__ o)
{
    int oc = threadIdx.x;
    __half* row = o + oc * 64;
#pragma unroll
    for (int j = 0; j < 64; j++) row[j] = __ushort_as_half((unsigned short)0);
#pragma unroll
    for (int j = 0; j < 27; j++) row[j] = __float2half_rn(w[oc * 27 + j]);
}
__global__ __launch_bounds__(256) void prep_w2(const float* __restrict__ w, __half* __restrict__ o)
{
    int oc = blockIdx.x;
    for (int k = threadIdx.x; k < 1152; k += 256) {
        int kk = k >> 7, ic = k & 127;
        o[oc * 1152 + k] = __float2half_rn(w[oc * 1152 + ic * 9 + kk]);
    }
}
__global__ __launch_bounds__(256) void prep_w3(const float* __restrict__ w, __half* __restrict__ o)
{
    int oc = blockIdx.x;
    for (int k = threadIdx.x; k < 2304; k += 256) {
        int kk = k >> 8, ic = k & 255;
        o[oc * 2304 + k] = __float2half_rn(w[oc * 2304 + ic * 9 + kk]);
    }
}

// ============================ conv1: fully fused (x fp32 -> h1 NHWC fp16) ============================
__global__ __launch_bounds__(256)
void conv1_kernel(const float* __restrict__ x, const __half* __restrict__ Bw,
                  const float* __restrict__ bias, const float* __restrict__ g,
                  const float* __restrict__ beta, const float* __restrict__ m,
                  const float* __restrict__ v, __half* __restrict__ out)
{
    extern __shared__ __align__(16) char smem[];
    __shared__ float scs[128], shs[128];
    float* in_s = (float*)smem;                 // 1920 floats
    const int A_OFF = 7680, B_OFF = 26112;

    int tid = threadIdx.x, wid = tid >> 5, lane = tid & 31;
    int wm = wid & 3, wn = wid >> 2;
    int rowbase = blockIdx.x * 128;
    int img = rowbase >> 10, p0 = rowbase & 1023;
    int oh0 = p0 >> 5;
    int ihb0 = 2 * oh0 - 1;

    if (tid < 128) {
        float sc = g[tid] / sqrtf(v[tid] + BN_EPS);
        scs[tid] = sc;
        shs[tid] = beta[tid] - m[tid] * sc + bias[tid] * sc;
    }

    uint32_t sb = smem_u32(smem);

#pragma unroll
    for (int i = 0; i < 4; i++) {
        int gi = tid + 256 * i; int rr = gi >> 3, gc = gi & 7;
        cp_async16(sb + B_OFF + rr * 144 + gc * 16, (const char*)Bw + (rr * 64 + gc * 8) * 2);
    }
    asm volatile("cp.async.commit_group;");

    const float* xim = x + (size_t)img * 12288;
    for (int i = tid; i < 1920; i += 256) {
        int ic = i / 640, rem = i - ic * 640;
        int r = rem >> 6, cidx = rem & 63;
        int gih = ihb0 + r;
        in_s[i] = (gih >= 0 && gih < 64) ? xim[ic * 4096 + (gih << 6) + cidx] : 0.f;
    }
    __syncthreads();

    // A-build on all 256 threads: warps 0-3 handle j0..13 (u32 0..6),
    // warps 4-7 handle j14..26 (u32 7..13) + zero pad (u32 14..31).
    {
        int row = tid & 127, seg = tid >> 7;
        int p = p0 + row;
        int oh = p >> 5, ow = p & 31;
        int ohl = oh - oh0;
        uint32_t* arow = (uint32_t*)(smem + A_OFF + row * 144);
        if (seg == 0) {
            uint32_t t[7];
#pragma unroll
            for (int i = 0; i < 7; i++) t[i] = 0;
#pragma unroll
            for (int j = 0; j < 14; j++) {
                int ic = j / 9, kk = j % 9, kh = kk / 3, kw = kk % 3;
                int lih = 2 * ohl + kh;
                int iw = 2 * ow - 1 + kw;
                float val = ((unsigned)iw < 64u) ? in_s[ic * 640 + (lih << 6) + iw] : 0.f;
                t[j >> 1] |= (uint32_t)__half_as_ushort(__float2half_rn(val)) << ((j & 1) * 16);
            }
#pragma unroll
            for (int i = 0; i < 7; i++) arow[i] = t[i];
        } else {
            uint32_t t[7];
#pragma unroll
            for (int i = 0; i < 7; i++) t[i] = 0;
#pragma unroll
            for (int j = 14; j < 27; j++) {
                int ic = j / 9, kk = j % 9, kh = kk / 3, kw = kk % 3;
                int lih = 2 * ohl + kh;
                int iw = 2 * ow - 1 + kw;
                float val = ((unsigned)iw < 64u) ? in_s[ic * 640 + (lih << 6) + iw] : 0.f;
                t[(j >> 1) - 7] |= (uint32_t)__half_as_ushort(__float2half_rn(val)) << ((j & 1) * 16);
            }
#pragma unroll
            for (int i = 0; i < 7; i++) arow[7 + i] = t[i];
#pragma unroll
            for (int i = 14; i < 32; i++) arow[i] = 0;
        }
    }
    asm volatile("cp.async.wait_group 0;");
    __syncthreads();

    float acc[2][8][4];
#pragma unroll
    for (int i = 0; i < 2; i++)
#pragma unroll
        for (int j = 0; j < 8; j++)
#pragma unroll
            for (int q = 0; q < 4; q++) acc[i][j][q] = 0.f;

    uint32_t ab = sb + A_OFF, bb = sb + B_OFF;
#pragma unroll
    for (int ks = 0; ks < 4; ks++) {
        uint32_t af[2][4];
#pragma unroll
        for (int mt = 0; mt < 2; mt++) {
            uint32_t addr = ab + (wm * 32 + mt * 16 + (lane & 15)) * 144
                            + ks * 32 + ((lane >> 4) << 4);
            ldsm_x4(af[mt], addr);
        }
#pragma unroll
        for (int nt2 = 0; nt2 < 4; nt2++) {
            uint32_t bf[4];
            uint32_t addr = bb + (wn * 64 + nt2 * 16 + (lane & 7) + (((lane >> 4) & 1) << 3)) * 144
                            + ks * 32 + (((lane >> 3) & 1) << 4);
            ldsm_x4(bf, addr);
#pragma unroll
            for (int mt = 0; mt < 2; mt++) {
                mma_f16(acc[mt][2 * nt2],     af[mt], bf);
                mma_f16(acc[mt][2 * nt2 + 1], af[mt], bf + 2);
            }
        }
    }
    __syncthreads();

    float* stage = (float*)smem;
#pragma unroll
    for (int mt = 0; mt < 2; mt++)
#pragma unroll
        for (int nt = 0; nt < 8; nt++) {
            int r0 = wm * 32 + mt * 16 + (lane >> 2);
            int c0 = wn * 64 + nt * 8 + 2 * (lane & 3);
            stage[r0 * 129 + c0]           = acc[mt][nt][0];
            stage[r0 * 129 + c0 + 1]       = acc[mt][nt][1];
            stage[(r0 + 8) * 129 + c0]     = acc[mt][nt][2];
            stage[(r0 + 8) * 129 + c0 + 1] = acc[mt][nt][3];
        }
    __syncthreads();

    __half2* o2 = (__half2*)out;
#pragma unroll
    for (int rblk = 0; rblk < 16; rblk++) {
        int r = wid * 16 + rblk;
        size_t base2 = ((size_t)(rowbase + r) * 128) >> 1;
#pragma unroll
        for (int cc = lane; cc < 64; cc += 32) {
            float y0 = stage[r * 129 + 2 * cc] * scs[2 * cc] + shs[2 * cc];
            float y1 = stage[r * 129 + 2 * cc + 1] * scs[2 * cc + 1] + shs[2 * cc + 1];
            y0 = y0 > 0.f ? y0 : SLOPE * y0;
            y1 = y1 > 0.f ? y1 : SLOPE * y1;
            o2[base2 + cc] = __floats2half2_rn(y0, y1);
        }
    }
}

// ============================ HMMA GEMM (fp16, fused gather; CONV 2/3) ============================
template<int CONV>
__global__ __launch_bounds__(256)
void gemm_kernel(const __half* __restrict__ A, const __half* __restrict__ Bw,
                 const float* __restrict__ bias, const float* __restrict__ g,
                 const float* __restrict__ beta, const float* __restrict__ m,
                 const float* __restrict__ v, void* __restrict__ out_v)
{
    constexpr int N  = (CONV == 2) ? 256 : 64;
    constexpr int KS = (CONV == 2) ? 1152 : 2304;
    constexpr int NC = KS / 64;
    constexpr int BN = N;
    constexpr int WN = BN / 2;
    constexpr int NT = WN / 8;
    constexpr int ABUF = 128 * 144;
    constexpr int BBUF = BN * 144;
    constexpr int BGI = (BN * 8) / 256;
    constexpr int P = BN + 1;

    extern __shared__ __align__(16) char smem[];
    __shared__ float scs[256], shs[256];

    int tid = threadIdx.x, wid = tid >> 5, lane = tid & 31;
    int wm = wid & 3, wn = wid >> 2;
    int rowbase = blockIdx.x * 128;
    int img0 = rowbase >> 8, p0 = rowbase & 255;

    if (tid < N) {
        float sc = g[tid] / sqrtf(v[tid] + BN_EPS);
        scs[tid] = sc;
        shs[tid] = beta[tid] - m[tid] * sc + bias[tid] * sc;
    }

    uint32_t sb = smem_u32(smem);

    float acc[2][NT][4];
#pragma unroll
    for (int i = 0; i < 2; i++)
#pragma unroll
        for (int j = 0; j < NT; j++)
#pragma unroll
            for (int q = 0; q < 4; q++) acc[i][j][q] = 0.f;

    auto issue_copy = [&](int c) {
        int buf = c & 1;
        uint32_t ab = sb + buf * (ABUF + BBUF);
        uint32_t bb = ab + ABUF;
        if (CONV == 2) {
            int kk = c >> 1, icg = c & 1;
            int kh = kk / 3, kw = kk - 3 * kh;
#pragma unroll
            for (int i = 0; i < 4; i++) {
                int gi = tid + 256 * i; int rr = gi >> 3, gc = gi & 7;
                int p = p0 + rr;
                int oh = p >> 4, ow = p & 15;
                int ih = 2 * oh - 1 + kh, iw = 2 * ow - 1 + kw;
                bool ok = ((unsigned)ih < 32u) && ((unsigned)iw < 32u);
                size_t off = (((size_t)img0 * 32 + (ok ? ih : 0)) * 32 + (ok ? iw : 0)) * 128
                             + icg * 64 + gc * 8;
                cp_async16z(ab + rr * 144 + gc * 16, (const char*)A + off * 2, ok ? 16 : 0);
            }
        } else {
            int kk = c >> 2, icg = c & 3;
            int kh = kk / 3, kw = kk - 3 * kh;
#pragma unroll
            for (int i = 0; i < 4; i++) {
                int gi = tid + 256 * i; int rr = gi >> 3, gc = gi & 7;
                int grow = rowbase + rr;
                int img = grow >> 6, p = grow & 63;
                int oh = p >> 3, ow = p & 7;
                int ih = 2 * oh - 1 + kh, iw = 2 * ow - 1 + kw;
                bool ok = ((unsigned)ih < 16u) && ((unsigned)iw < 16u);
                size_t off = (((size_t)img * 16 + (ok ? ih : 0)) * 16 + (ok ? iw : 0)) * 256
                             + icg * 64 + gc * 8;
                cp_async16z(ab + rr * 144 + gc * 16, (const char*)A + off * 2, ok ? 16 : 0);
            }
        }
#pragma unroll
        for (int i = 0; i < BGI; i++) {
            int gi = tid + 256 * i; int rr = gi >> 3, gc = gi & 7;
            cp_async16(bb + rr * 144 + gc * 16,
                       (const char*)Bw + ((size_t)rr * KS + c * 64) * 2 + gc * 16);
        }
        asm volatile("cp.async.commit_group;");
    };

    issue_copy(0);
    for (int c = 0; c < NC; c++) {
        if (c + 1 < NC) {
            issue_copy(c + 1);
            asm volatile("cp.async.wait_group 1;");
        } else {
            asm volatile("cp.async.wait_group 0;");
        }
        __syncthreads();

        int buf = c & 1;
        uint32_t ab = sb + buf * (ABUF + BBUF);
        uint32_t bb = ab + ABUF;
#pragma unroll
        for (int ks = 0; ks < 4; ks++) {
            uint32_t af[2][4];
#pragma unroll
            for (int mt = 0; mt < 2; mt++) {
                uint32_t addr = ab + (wm * 32 + mt * 16 + (lane & 15)) * 144
                                + ks * 32 + ((lane >> 4) << 4);
                ldsm_x4(af[mt], addr);
            }
#pragma unroll
            for (int nt2 = 0; nt2 < NT / 2; nt2++) {
                uint32_t bf[4];
                uint32_t addr = bb + (wn * WN + nt2 * 16 + (lane & 7) + (((lane >> 4) & 1) << 3)) * 144
                                + ks * 32 + (((lane >> 3) & 1) << 4);
                ldsm_x4(bf, addr);
#pragma unroll
                for (int mt = 0; mt < 2; mt++) {
                    mma_f16(acc[mt][2 * nt2],     af[mt], bf);
                    mma_f16(acc[mt][2 * nt2 + 1], af[mt], bf + 2);
                }
            }
        }
        __syncthreads();
    }

    if (CONV == 3) {
        float* stage = (float*)smem;
#pragma unroll
        for (int mt = 0; mt < 2; mt++)
#pragma unroll
            for (int nt = 0; nt < NT; nt++) {
                int r0 = wm * 32 + mt * 16 + (lane >> 2);
                int c0 = wn * WN + nt * 8 + 2 * (lane & 3);
                stage[r0 * P + c0]           = acc[mt][nt][0];
                stage[r0 * P + c0 + 1]       = acc[mt][nt][1];
                stage[(r0 + 8) * P + c0]     = acc[mt][nt][2];
                stage[(r0 + 8) * P + c0 + 1] = acc[mt][nt][3];
            }
        __syncthreads();
#pragma unroll
        for (int j = 0; j < BN / 8; j++) {
            int colL = wid * (BN / 8) + j;
            float sc = scs[colL], sh = shs[colL];
#pragma unroll
            for (int it = 0; it < 4; it++) {
                int r = it * 32 + lane;
                float y = stage[r * P + colL] * sc + sh;
                y = y > 0.f ? y : SLOPE * y;
                int grow = rowbase + r;
                int img = grow >> 6, p = grow & 63;
                ((float*)out_v)[(size_t)img * 4096 + colL * 64 + p] = y;
            }
        }
    } else {
        float* stage = (float*)smem;
        __half2* o2 = (__half2*)out_v;
#pragma unroll
        for (int h = 0; h < 2; h++) {
            __syncthreads();
            if (wn == h) {
#pragma unroll
                for (int mt = 0; mt < 2; mt++)
#pragma unroll
                    for (int nt = 0; nt < NT; nt++) {
                        int r0 = wm * 32 + mt * 16 + (lane >> 2);
                        int c0 = nt * 8 + 2 * (lane & 3);
                        stage[r0 * 129 + c0]           = acc[mt][nt][0];
                        stage[r0 * 129 + c0 + 1]       = acc[mt][nt][1];
                        stage[(r0 + 8) * 129 + c0]     = acc[mt][nt][2];
                        stage[(r0 + 8) * 129 + c0 + 1] = acc[mt][nt][3];
                    }
            }
            __syncthreads();
#pragma unroll
            for (int rblk = 0; rblk < 16; rblk++) {
                int r = wid * 16 + rblk;
                size_t base2 = ((size_t)(rowbase + r) * 256 + h * 128) >> 1;
#pragma unroll
                for (int cc = lane; cc < 64; cc += 32) {
                    int gc = h * 128 + 2 * cc;
                    float y0 = stage[r * 129 + 2 * cc] * scs[gc] + shs[gc];
                    float y1 = stage[r * 129 + 2 * cc + 1] * scs[gc + 1] + shs[gc + 1];
                    y0 = y0 > 0.f ? y0 : SLOPE * y0;
                    y1 = y1 > 0.f ? y1 : SLOPE * y1;
                    o2[base2 + cc] = __floats2half2_rn(y0, y1);
                }
            }
        }
    }
}

// ============================ k-means ============================
__global__ __launch_bounds__(256) void normalize_kernel(float* __restrict__ data)
{
    int row = blockIdx.x, tid = threadIdx.x;
    float* dr = data + row * 4096;
    float vals[16];
    float s = 0.f;
#pragma unroll
    for (int i = 0; i < 16; i++) { vals[i] = dr[tid + i * 256]; s = fmaf(vals[i], vals[i], s); }
    __shared__ float sm[9];
    int lane = tid & 31, warp = tid >> 5;
#pragma unroll
    for (int off = 16; off > 0; off >>= 1) s += __shfl_down_sync(0xffffffffu, s, off);
    if (lane == 0) sm[warp] = s;
    __syncthreads();
    if (tid == 0) {
        float t = 0.f;
        for (int w = 0; w < 8; w++) t += sm[w];
        sm[8] = 1.f / sqrtf(t);
    }
    __syncthreads();
    float inv = sm[8];
#pragma unroll
    for (int i = 0; i < 16; i++) dr[tid + i * 256] = vals[i] * inv;
}

__global__ __launch_bounds__(256) void gram_kernel(const float* __restrict__ data, float* __restrict__ G)
{
    __shared__ float at[16][129];
    __shared__ float bt[16][129];
    int tid = threadIdx.x;
    int ty = tid >> 4, tx = tid & 15;
    int r0 = blockIdx.y * 16, c0 = blockIdx.x * 16;
    float acc = 0.f;
    for (int kc = 0; kc < 4096; kc += 128) {
        __syncthreads();
        for (int i = tid; i < 2048; i += 256) {
            int rr = i >> 7, cc = i & 127;
            at[rr][cc] = data[(size_t)(r0 + rr) * 4096 + kc + cc];
            bt[rr][cc] = data[(size_t)(c0 + rr) * 4096 + kc + cc];
        }
        __syncthreads();
#pragma unroll 16
        for (int k = 0; k < 128; k++) acc = fmaf(at[ty][k], bt[tx][k], acc);
    }
    G[(r0 + ty) * 256 + c0 + tx] = acc;
}

__global__ __launch_bounds__(256) void dist0_kernel(
    const float* __restrict__ data, const float* __restrict__ mu, float* __restrict__ dout)
{
    int row = blockIdx.x, tid = threadIdx.x;
    const float* dr = data + row * 4096;
    float acc[16];
#pragma unroll
    for (int k = 0; k < 16; k++) acc[k] = 0.f;
#pragma unroll 4
    for (int i = 0; i < 16; i++) {
        int j = tid + i * 256;
        float dj = __ldg(dr + j);
#pragma unroll
        for (int k = 0; k < 16; k++) acc[k] = fmaf(dj, __ldg(mu + k * 4096 + j), acc[k]);
    }
    __shared__ float wsum[8][16];
    int lane = tid & 31, warp = tid >> 5;
#pragma unroll
    for (int k = 0; k < 16; k++) {
        float vv = acc[k];
#pragma unroll
        for (int off = 16; off > 0; off >>= 1) vv += __shfl_down_sync(0xffffffffu, vv, off);
        if (lane == 0) wsum[warp][k] = vv;
    }
    __syncthreads();
    if (tid < 16) {
        float s = 0.f;
#pragma unroll
        for (int w = 0; w < 8; w++) s += wsum[w][tid];
        dout[row * 16 + tid] = s;
    }
}

// one soft-kmeans step: grid(16) x 256 threads = 16 rows x 16 k per block.
// dist[row][k] = (G @ rprev)[row][k] / cs[k];  cs from 16 per-block partials.
// writes raw softmax r + per-block partial colsums (all deterministic).
__global__ __launch_bounds__(256) void kiter_kernel(
    const float* __restrict__ G, const float* __restrict__ D0,
    const float* __restrict__ rprev, const float* __restrict__ psprev,
    float* __restrict__ rout, float* __restrict__ psout, int it)
{
    __shared__ float ps[16][16];
    int tid = threadIdx.x;
    int rloc = tid >> 4, tk = tid & 15;
    int row = blockIdx.x * 16 + rloc;

    float L;
    if (it == 0) {
        L = CT * __ldg(D0 + row * 16 + tk);
    } else {
        float cs = 0.f;
#pragma unroll
        for (int b = 0; b < 16; b++) cs += __ldg(psprev + b * 16 + tk);
        float acc = 0.f;
        const float4* g4 = (const float4*)(G + (size_t)row * 256);
#pragma unroll 8
        for (int n4 = 0; n4 < 64; n4++) {
            float4 gv = __ldg(g4 + n4);
            acc = fmaf(gv.x, __ldg(rprev + (n4 * 4 + 0) * 16 + tk), acc);
            acc = fmaf(gv.y, __ldg(rprev + (n4 * 4 + 1) * 16 + tk), acc);
            acc = fmaf(gv.z, __ldg(rprev + (n4 * 4 + 2) * 16 + tk), acc);
            acc = fmaf(gv.w, __ldg(rprev + (n4 * 4 + 3) * 16 + tk), acc);
        }
        L = CT * acc / cs;
    }
    // softmax over the 16 k-lanes
    float mx = L;
#pragma unroll
    for (int d = 8; d >= 1; d >>= 1) mx = fmaxf(mx, __shfl_xor_sync(0xffffffffu, mx, d));
    float e = expf(L - mx);
    float s = e;
#pragma unroll
    for (int d = 8; d >= 1; d >>= 1) s += __shfl_xor_sync(0xffffffffu, s, d);
    float r = e / s;
    rout[row * 16 + tk] = r;

    ps[rloc][tk] = r;
    __syncthreads();
    if (tid < 16) {
        float ss = 0.f;
#pragma unroll
        for (int rr = 0; rr < 16; rr++) ss += ps[rr][tid];
        psout[blockIdx.x * 16 + tid] = ss;
    }
}

// ============================ host ============================
extern "C" void kernel_launch(void* const* d_in, const int* in_sizes, int n_in,
                              void* d_out, int out_size)
{
    const float* x   = (const float*)d_in[0];
    const float* w1  = (const float*)d_in[1];
    const float* b1  = (const float*)d_in[2];
    const float* g1  = (const float*)d_in[3];
    const float* be1 = (const float*)d_in[4];
    const float* m1  = (const float*)d_in[5];
    const float* v1  = (const float*)d_in[6];
    const float* w2  = (const float*)d_in[7];
    const float* b2  = (const float*)d_in[8];
    const float* g2  = (const float*)d_in[9];
    const float* be2 = (const float*)d_in[10];
    const float* m2  = (const float*)d_in[11];
    const float* v2  = (const float*)d_in[12];
    const float* w3  = (const float*)d_in[13];
    const float* b3  = (const float*)d_in[14];
    const float* g3  = (const float*)d_in[15];
    const float* be3 = (const float*)d_in[16];
    const float* m3  = (const float*)d_in[17];
    const float* v3  = (const float*)d_in[18];
    const float* mu0 = (const float*)d_in[19];

    float *data, *G, *D0, *Ra, *Rb, *PSa, *PSb;
    __half *h1, *h2, *B1, *B2, *B3;
    cudaGetSymbolAddress((void**)&h1, g_h1);
    cudaGetSymbolAddress((void**)&h2, g_h2);
    cudaGetSymbolAddress((void**)&data, g_data);
    cudaGetSymbolAddress((void**)&G, g_G);
    cudaGetSymbolAddress((void**)&D0, g_D0);
    cudaGetSymbolAddress((void**)&Ra, g_Ra);
    cudaGetSymbolAddress((void**)&Rb, g_Rb);
    cudaGetSymbolAddress((void**)&PSa, g_PSa);
    cudaGetSymbolAddress((void**)&PSb, g_PSb);
    cudaGetSymbolAddress((void**)&B1, g_B1);
    cudaGetSymbolAddress((void**)&B2, g_B2);
    cudaGetSymbolAddress((void**)&B3, g_B3);

    const int smem_c1 = 66048;
    const int smem_g2 = 2 * (128 * 144 + 256 * 144);   // 110592
    const int smem_g3 = 2 * (128 * 144 + 64 * 144);    // 55296
    cudaFuncSetAttribute(conv1_kernel, cudaFuncAttributeMaxDynamicSharedMemorySize, smem_c1);
    cudaFuncSetAttribute(gemm_kernel<2>, cudaFuncAttributeMaxDynamicSharedMemorySize, smem_g2);
    cudaFuncSetAttribute(gemm_kernel<3>, cudaFuncAttributeMaxDynamicSharedMemorySize, smem_g3);

    // order chosen so gemm2 is launch #4 (the slot ncu captures)
    prep_w1<<<1, 128>>>(w1, B1);
    conv1_kernel<<<2048, 256, smem_c1>>>(x, B1, b1, g1, be1, m1, v1, h1);
    prep_w2<<<256, 256>>>(w2, B2);
    gemm_kernel<2><<<dim3(512, 1), 256, smem_g2>>>(h1, B2, b2, g2, be2, m2, v2, h2);
    prep_w3<<<64, 256>>>(w3, B3);
    gemm_kernel<3><<<dim3(128, 1), 256, smem_g3>>>(h2, B3, b3, g3, be3, m3, v3, data);

    normalize_kernel<<<256, 256>>>(data);
    gram_kernel<<<dim3(16, 16), 256>>>(data, G);
    dist0_kernel<<<256, 256>>>(data, mu0, D0);

    float* rin = Ra;  float* rout = Rb;
    float* pin = PSa; float* pout = PSb;
    for (int it = 0; it < 12; it++) {
        float* rdst = (it == 11) ? (float*)d_out : rout;
        kiter_kernel<<<16, 256>>>(G, D0, rin, pin, rdst, pout, it);
        float* t = rin; rin = rout; rout = t;
        t = pin; pin = pout; pout = t;
    }
}

// round 14
// speedup vs baseline: 1.3548x; 1.0453x over previous
#include <cuda_runtime.h>
#include <cuda_fp16.h>
#include <math.h>
#include <stdint.h>

#define BN_EPS 1e-3f
#define SLOPE  0.1f
#define CT     30.0f

// ============================ scratch globals ============================
__device__ __half g_h1[256 * 32 * 32 * 128];  // conv1 out NHWC fp16
__device__ __half g_h2[256 * 16 * 16 * 256];  // conv2 out NHWC fp16
__device__ float g_data[256 * 4096];
__device__ float g_G[256 * 256];
__device__ float g_D0[256 * 16];
__device__ float g_Ra[256 * 16];
__device__ float g_Rb[256 * 16];
__device__ float g_PSa[16 * 16];
__device__ float g_PSb[16 * 16];
__device__ __half g_B1[128 * 64];
__device__ __half g_B2[256 * 1152];           // k = kk*128 + ic
__device__ __half g_B3[64 * 2304];            // k = kk*256 + ic

__device__ __forceinline__ uint32_t smem_u32(const void* p) {
    uint32_t a;
    asm("{ .reg .u64 t; cvta.to.shared.u64 t, %1; cvt.u32.u64 %0, t; }" : "=r"(a) : "l"(p));
    return a;
}
__device__ __forceinline__ void cp_async16(uint32_t dst, const void* src) {
    asm volatile("cp.async.cg.shared.global [%0], [%1], 16;" :: "r"(dst), "l"(src));
}
__device__ __forceinline__ void cp_async16z(uint32_t dst, const void* src, int szbytes) {
    asm volatile("cp.async.cg.shared.global [%0], [%1], 16, %2;"
                 :: "r"(dst), "l"(src), "r"(szbytes));
}
__device__ __forceinline__ void ldsm_x4(uint32_t* f, uint32_t addr) {
    asm volatile("ldmatrix.sync.aligned.m8n8.x4.shared.b16 {%0,%1,%2,%3}, [%4];"
                 : "=r"(f[0]), "=r"(f[1]), "=r"(f[2]), "=r"(f[3]) : "r"(addr));
}
__device__ __forceinline__ void mma_f16(float* d, const uint32_t* a, const uint32_t* b) {
    asm volatile(
        "mma.sync.aligned.m16n8k16.row.col.f32.f16.f16.f32 "
        "{%0,%1,%2,%3}, {%4,%5,%6,%7}, {%8,%9}, {%0,%1,%2,%3};"
        : "+f"(d[0]), "+f"(d[1]), "+f"(d[2]), "+f"(d[3])
        : "r"(a[0]), "r"(a[1]), "r"(a[2]), "r"(a[3]), "r"(b[0]), "r"(b[1]));
}

// ============================ weight prep ============================
__global__ __launch_bounds__(128) void prep_w1(const float* __restrict__ w, __half* __restrict__ o)
{
    int oc = threadIdx.x;
    __half* row = o + oc * 64;
#pragma unroll
    for (int j = 0; j < 64; j++) row[j] = __ushort_as_half((unsigned short)0);
#pragma unroll
    for (int j = 0; j < 27; j++) row[j] = __float2half_rn(w[oc * 27 + j]);
}
__global__ __launch_bounds__(256) void prep_w2(const float* __restrict__ w, __half* __restrict__ o)
{
    int oc = blockIdx.x;
    for (int k = threadIdx.x; k < 1152; k += 256) {
        int kk = k >> 7, ic = k & 127;
        o[oc * 1152 + k] = __float2half_rn(w[oc * 1152 + ic * 9 + kk]);
    }
}
__global__ __launch_bounds__(256) void prep_w3(const float* __restrict__ w, __half* __restrict__ o)
{
    int oc = blockIdx.x;
    for (int k = threadIdx.x; k < 2304; k += 256) {
        int kk = k >> 8, ic = k & 255;
        o[oc * 2304 + k] = __float2half_rn(w[oc * 2304 + ic * 9 + kk]);
    }
}

// ============================ conv1: fully fused (x fp32 -> h1 NHWC fp16) ============================
__global__ __launch_bounds__(256)
void conv1_kernel(const float* __restrict__ x, const __half* __restrict__ Bw,
                  const float* __restrict__ bias, const float* __restrict__ g,
                  const float* __restrict__ beta, const float* __restrict__ m,
                  const float* __restrict__ v, __half* __restrict__ out)
{
    extern __shared__ __align__(16) char smem[];
    __shared__ float scs[128], shs[128];
    float* in_s = (float*)smem;                 // 1920 floats
    const int A_OFF = 7680, B_OFF = 26112;

    int tid = threadIdx.x, wid = tid >> 5, lane = tid & 31;
    int wm = wid & 3, wn = wid >> 2;
    int rowbase = blockIdx.x * 128;
    int img = rowbase >> 10, p0 = rowbase & 1023;
    int oh0 = p0 >> 5;
    int ihb0 = 2 * oh0 - 1;

    if (tid < 128) {
        float sc = g[tid] / sqrtf(v[tid] + BN_EPS);
        scs[tid] = sc;
        shs[tid] = beta[tid] - m[tid] * sc + bias[tid] * sc;
    }

    uint32_t sb = smem_u32(smem);

#pragma unroll
    for (int i = 0; i < 4; i++) {
        int gi = tid + 256 * i; int rr = gi >> 3, gc = gi & 7;
        cp_async16(sb + B_OFF + rr * 144 + gc * 16, (const char*)Bw + (rr * 64 + gc * 8) * 2);
    }
    asm volatile("cp.async.commit_group;");

    const float* xim = x + (size_t)img * 12288;
    for (int i = tid; i < 1920; i += 256) {
        int ic = i / 640, rem = i - ic * 640;
        int r = rem >> 6, cidx = rem & 63;
        int gih = ihb0 + r;
        in_s[i] = (gih >= 0 && gih < 64) ? xim[ic * 4096 + (gih << 6) + cidx] : 0.f;
    }
    __syncthreads();

    {
        int row = tid & 127, seg = tid >> 7;
        int p = p0 + row;
        int oh = p >> 5, ow = p & 31;
        int ohl = oh - oh0;
        uint32_t* arow = (uint32_t*)(smem + A_OFF + row * 144);
        if (seg == 0) {
            uint32_t t[7];
#pragma unroll
            for (int i = 0; i < 7; i++) t[i] = 0;
#pragma unroll
            for (int j = 0; j < 14; j++) {
                int ic = j / 9, kk = j % 9, kh = kk / 3, kw = kk % 3;
                int lih = 2 * ohl + kh;
                int iw = 2 * ow - 1 + kw;
                float val = ((unsigned)iw < 64u) ? in_s[ic * 640 + (lih << 6) + iw] : 0.f;
                t[j >> 1] |= (uint32_t)__half_as_ushort(__float2half_rn(val)) << ((j & 1) * 16);
            }
#pragma unroll
            for (int i = 0; i < 7; i++) arow[i] = t[i];
        } else {
            uint32_t t[7];
#pragma unroll
            for (int i = 0; i < 7; i++) t[i] = 0;
#pragma unroll
            for (int j = 14; j < 27; j++) {
                int ic = j / 9, kk = j % 9, kh = kk / 3, kw = kk % 3;
                int lih = 2 * ohl + kh;
                int iw = 2 * ow - 1 + kw;
                float val = ((unsigned)iw < 64u) ? in_s[ic * 640 + (lih << 6) + iw] : 0.f;
                t[(j >> 1) - 7] |= (uint32_t)__half_as_ushort(__float2half_rn(val)) << ((j & 1) * 16);
            }
#pragma unroll
            for (int i = 0; i < 7; i++) arow[7 + i] = t[i];
#pragma unroll
            for (int i = 14; i < 32; i++) arow[i] = 0;
        }
    }
    asm volatile("cp.async.wait_group 0;");
    __syncthreads();

    float acc[2][8][4];
#pragma unroll
    for (int i = 0; i < 2; i++)
#pragma unroll
        for (int j = 0; j < 8; j++)
#pragma unroll
            for (int q = 0; q < 4; q++) acc[i][j][q] = 0.f;

    uint32_t ab = sb + A_OFF, bb = sb + B_OFF;
#pragma unroll
    for (int ks = 0; ks < 4; ks++) {
        uint32_t af[2][4];
#pragma unroll
        for (int mt = 0; mt < 2; mt++) {
            uint32_t addr = ab + (wm * 32 + mt * 16 + (lane & 15)) * 144
                            + ks * 32 + ((lane >> 4) << 4);
            ldsm_x4(af[mt], addr);
        }
#pragma unroll
        for (int nt2 = 0; nt2 < 4; nt2++) {
            uint32_t bf[4];
            uint32_t addr = bb + (wn * 64 + nt2 * 16 + (lane & 7) + (((lane >> 4) & 1) << 3)) * 144
                            + ks * 32 + (((lane >> 3) & 1) << 4);
            ldsm_x4(bf, addr);
#pragma unroll
            for (int mt = 0; mt < 2; mt++) {
                mma_f16(acc[mt][2 * nt2],     af[mt], bf);
                mma_f16(acc[mt][2 * nt2 + 1], af[mt], bf + 2);
            }
        }
    }
    __syncthreads();

    float* stage = (float*)smem;
#pragma unroll
    for (int mt = 0; mt < 2; mt++)
#pragma unroll
        for (int nt = 0; nt < 8; nt++) {
            int r0 = wm * 32 + mt * 16 + (lane >> 2);
            int c0 = wn * 64 + nt * 8 + 2 * (lane & 3);
            stage[r0 * 129 + c0]           = acc[mt][nt][0];
            stage[r0 * 129 + c0 + 1]       = acc[mt][nt][1];
            stage[(r0 + 8) * 129 + c0]     = acc[mt][nt][2];
            stage[(r0 + 8) * 129 + c0 + 1] = acc[mt][nt][3];
        }
    __syncthreads();

    __half2* o2 = (__half2*)out;
#pragma unroll
    for (int rblk = 0; rblk < 16; rblk++) {
        int r = wid * 16 + rblk;
        size_t base2 = ((size_t)(rowbase + r) * 128) >> 1;
#pragma unroll
        for (int cc = lane; cc < 64; cc += 32) {
            float y0 = stage[r * 129 + 2 * cc] * scs[2 * cc] + shs[2 * cc];
            float y1 = stage[r * 129 + 2 * cc + 1] * scs[2 * cc + 1] + shs[2 * cc + 1];
            y0 = y0 > 0.f ? y0 : SLOPE * y0;
            y1 = y1 > 0.f ? y1 : SLOPE * y1;
            o2[base2 + cc] = __floats2half2_rn(y0, y1);
        }
    }
}

// ============================ HMMA GEMM (fp16, fused gather; CONV 2/3) ============================
// CONV2: BN=128, grid (512, 2) -> acc 64/thread, 2 CTAs/SM.
// CONV3: BN=64,  grid (128, 1) -> acc 32/thread, 2 CTAs/SM.
template<int CONV>
__global__ __launch_bounds__(256, 2)
void gemm_kernel(const __half* __restrict__ A, const __half* __restrict__ Bw,
                 const float* __restrict__ bias, const float* __restrict__ g,
                 const float* __restrict__ beta, const float* __restrict__ m,
                 const float* __restrict__ v, void* __restrict__ out_v)
{
    constexpr int N  = (CONV == 2) ? 256 : 64;
    constexpr int KS = (CONV == 2) ? 1152 : 2304;
    constexpr int NC = KS / 64;
    constexpr int BN = (CONV == 2) ? 128 : 64;
    constexpr int WN = BN / 2;
    constexpr int NT = WN / 8;
    constexpr int ABUF = 128 * 144;
    constexpr int BBUF = BN * 144;
    constexpr int BGI = (BN * 8) / 256;
    constexpr int P = BN + 1;

    extern __shared__ __align__(16) char smem[];
    __shared__ float scs[BN], shs[BN];

    int tid = threadIdx.x, wid = tid >> 5, lane = tid & 31;
    int wm = wid & 3, wn = wid >> 2;
    int rowbase = blockIdx.x * 128;
    int nb0 = blockIdx.y * BN;
    int img0 = rowbase >> 8, p0 = rowbase & 255;

    if (tid < BN) {
        int gcol = nb0 + tid;
        float sc = g[gcol] / sqrtf(v[gcol] + BN_EPS);
        scs[tid] = sc;
        shs[tid] = beta[gcol] - m[gcol] * sc + bias[gcol] * sc;
    }

    uint32_t sb = smem_u32(smem);

    float acc[2][NT][4];
#pragma unroll
    for (int i = 0; i < 2; i++)
#pragma unroll
        for (int j = 0; j < NT; j++)
#pragma unroll
            for (int q = 0; q < 4; q++) acc[i][j][q] = 0.f;

    auto issue_copy = [&](int c) {
        int buf = c & 1;
        uint32_t ab = sb + buf * (ABUF + BBUF);
        uint32_t bb = ab + ABUF;
        if (CONV == 2) {
            int kk = c >> 1, icg = c & 1;
            int kh = kk / 3, kw = kk - 3 * kh;
#pragma unroll
            for (int i = 0; i < 4; i++) {
                int gi = tid + 256 * i; int rr = gi >> 3, gc = gi & 7;
                int p = p0 + rr;
                int oh = p >> 4, ow = p & 15;
                int ih = 2 * oh - 1 + kh, iw = 2 * ow - 1 + kw;
                bool ok = ((unsigned)ih < 32u) && ((unsigned)iw < 32u);
                size_t off = (((size_t)img0 * 32 + (ok ? ih : 0)) * 32 + (ok ? iw : 0)) * 128
                             + icg * 64 + gc * 8;
                cp_async16z(ab + rr * 144 + gc * 16, (const char*)A + off * 2, ok ? 16 : 0);
            }
        } else {
            int kk = c >> 2, icg = c & 3;
            int kh = kk / 3, kw = kk - 3 * kh;
#pragma unroll
            for (int i = 0; i < 4; i++) {
                int gi = tid + 256 * i; int rr = gi >> 3, gc = gi & 7;
                int grow = rowbase + rr;
                int img = grow >> 6, p = grow & 63;
                int oh = p >> 3, ow = p & 7;
                int ih = 2 * oh - 1 + kh, iw = 2 * ow - 1 + kw;
                bool ok = ((unsigned)ih < 16u) && ((unsigned)iw < 16u);
                size_t off = (((size_t)img * 16 + (ok ? ih : 0)) * 16 + (ok ? iw : 0)) * 256
                             + icg * 64 + gc * 8;
                cp_async16z(ab + rr * 144 + gc * 16, (const char*)A + off * 2, ok ? 16 : 0);
            }
        }
#pragma unroll
        for (int i = 0; i < BGI; i++) {
            int gi = tid + 256 * i; int rr = gi >> 3, gc = gi & 7;
            cp_async16(bb + rr * 144 + gc * 16,
                       (const char*)Bw + ((size_t)(nb0 + rr) * KS + c * 64) * 2 + gc * 16);
        }
        asm volatile("cp.async.commit_group;");
    };

    issue_copy(0);
    for (int c = 0; c < NC; c++) {
        if (c + 1 < NC) {
            issue_copy(c + 1);
            asm volatile("cp.async.wait_group 1;");
        } else {
            asm volatile("cp.async.wait_group 0;");
        }
        __syncthreads();

        int buf = c & 1;
        uint32_t ab = sb + buf * (ABUF + BBUF);
        uint32_t bb = ab + ABUF;
#pragma unroll
        for (int ks = 0; ks < 4; ks++) {
            uint32_t af[2][4];
#pragma unroll
            for (int mt = 0; mt < 2; mt++) {
                uint32_t addr = ab + (wm * 32 + mt * 16 + (lane & 15)) * 144
                                + ks * 32 + ((lane >> 4) << 4);
                ldsm_x4(af[mt], addr);
            }
#pragma unroll
            for (int nt2 = 0; nt2 < NT / 2; nt2++) {
                uint32_t bf[4];
                uint32_t addr = bb + (wn * WN + nt2 * 16 + (lane & 7) + (((lane >> 4) & 1) << 3)) * 144
                                + ks * 32 + (((lane >> 3) & 1) << 4);
                ldsm_x4(bf, addr);
#pragma unroll
                for (int mt = 0; mt < 2; mt++) {
                    mma_f16(acc[mt][2 * nt2],     af[mt], bf);
                    mma_f16(acc[mt][2 * nt2 + 1], af[mt], bf + 2);
                }
            }
        }
        __syncthreads();
    }

    float* stage = (float*)smem;
#pragma unroll
    for (int mt = 0; mt < 2; mt++)
#pragma unroll
        for (int nt = 0; nt < NT; nt++) {
            int r0 = wm * 32 + mt * 16 + (lane >> 2);
            int c0 = wn * WN + nt * 8 + 2 * (lane & 3);
            stage[r0 * P + c0]           = acc[mt][nt][0];
            stage[r0 * P + c0 + 1]       = acc[mt][nt][1];
            stage[(r0 + 8) * P + c0]     = acc[mt][nt][2];
            stage[(r0 + 8) * P + c0 + 1] = acc[mt][nt][3];
        }
    __syncthreads();

    if (CONV == 3) {
#pragma unroll
        for (int j = 0; j < BN / 8; j++) {
            int colL = wid * (BN / 8) + j;
            float sc = scs[colL], sh = shs[colL];
#pragma unroll
            for (int it = 0; it < 4; it++) {
                int r = it * 32 + lane;
                float y = stage[r * P + colL] * sc + sh;
                y = y > 0.f ? y : SLOPE * y;
                int grow = rowbase + r;
                int img = grow >> 6, p = grow & 63;
                ((float*)out_v)[(size_t)img * 4096 + colL * 64 + p] = y;
            }
        }
    } else {
        __half2* o2 = (__half2*)out_v;
#pragma unroll
        for (int rblk = 0; rblk < 16; rblk++) {
            int r = wid * 16 + rblk;
            size_t base2 = ((size_t)(rowbase + r) * 256 + nb0) >> 1;
#pragma unroll
            for (int cc = lane; cc < BN / 2; cc += 32) {
                float y0 = stage[r * P + 2 * cc] * scs[2 * cc] + shs[2 * cc];
                float y1 = stage[r * P + 2 * cc + 1] * scs[2 * cc + 1] + shs[2 * cc + 1];
                y0 = y0 > 0.f ? y0 : SLOPE * y0;
                y1 = y1 > 0.f ? y1 : SLOPE * y1;
                o2[base2 + cc] = __floats2half2_rn(y0, y1);
            }
        }
    }
}

// ============================ k-means ============================
__global__ __launch_bounds__(256) void normalize_kernel(float* __restrict__ data)
{
    int row = blockIdx.x, tid = threadIdx.x;
    float* dr = data + row * 4096;
    float vals[16];
    float s = 0.f;
#pragma unroll
    for (int i = 0; i < 16; i++) { vals[i] = dr[tid + i * 256]; s = fmaf(vals[i], vals[i], s); }
    __shared__ float sm[9];
    int lane = tid & 31, warp = tid >> 5;
#pragma unroll
    for (int off = 16; off > 0; off >>= 1) s += __shfl_down_sync(0xffffffffu, s, off);
    if (lane == 0) sm[warp] = s;
    __syncthreads();
    if (tid == 0) {
        float t = 0.f;
        for (int w = 0; w < 8; w++) t += sm[w];
        sm[8] = 1.f / sqrtf(t);
    }
    __syncthreads();
    float inv = sm[8];
#pragma unroll
    for (int i = 0; i < 16; i++) dr[tid + i * 256] = vals[i] * inv;
}

__global__ __launch_bounds__(256) void gram_kernel(const float* __restrict__ data, float* __restrict__ G)
{
    __shared__ float at[16][129];
    __shared__ float bt[16][129];
    int tid = threadIdx.x;
    int ty = tid >> 4, tx = tid & 15;
    int r0 = blockIdx.y * 16, c0 = blockIdx.x * 16;
    float acc = 0.f;
    for (int kc = 0; kc < 4096; kc += 128) {
        __syncthreads();
        for (int i = tid; i < 2048; i += 256) {
            int rr = i >> 7, cc = i & 127;
            at[rr][cc] = data[(size_t)(r0 + rr) * 4096 + kc + cc];
            bt[rr][cc] = data[(size_t)(c0 + rr) * 4096 + kc + cc];
        }
        __syncthreads();
#pragma unroll 16
        for (int k = 0; k < 128; k++) acc = fmaf(at[ty][k], bt[tx][k], acc);
    }
    G[(r0 + ty) * 256 + c0 + tx] = acc;
}

__global__ __launch_bounds__(256) void dist0_kernel(
    const float* __restrict__ data, const float* __restrict__ mu, float* __restrict__ dout)
{
    int row = blockIdx.x, tid = threadIdx.x;
    const float* dr = data + row * 4096;
    float acc[16];
#pragma unroll
    for (int k = 0; k < 16; k++) acc[k] = 0.f;
#pragma unroll 4
    for (int i = 0; i < 16; i++) {
        int j = tid + i * 256;
        float dj = __ldg(dr + j);
#pragma unroll
        for (int k = 0; k < 16; k++) acc[k] = fmaf(dj, __ldg(mu + k * 4096 + j), acc[k]);
    }
    __shared__ float wsum[8][16];
    int lane = tid & 31, warp = tid >> 5;
#pragma unroll
    for (int k = 0; k < 16; k++) {
        float vv = acc[k];
#pragma unroll
        for (int off = 16; off > 0; off >>= 1) vv += __shfl_down_sync(0xffffffffu, vv, off);
        if (lane == 0) wsum[warp][k] = vv;
    }
    __syncthreads();
    if (tid < 16) {
        float s = 0.f;
#pragma unroll
        for (int w = 0; w < 8; w++) s += wsum[w][tid];
        dout[row * 16 + tid] = s;
    }
}

__global__ __launch_bounds__(256) void kiter_kernel(
    const float* __restrict__ G, const float* __restrict__ D0,
    const float* __restrict__ rprev, const float* __restrict__ psprev,
    float* __restrict__ rout, float* __restrict__ psout, int it)
{
    __shared__ float ps[16][16];
    int tid = threadIdx.x;
    int rloc = tid >> 4, tk = tid & 15;
    int row = blockIdx.x * 16 + rloc;

    float L;
    if (it == 0) {
        L = CT * __ldg(D0 + row * 16 + tk);
    } else {
        float cs = 0.f;
#pragma unroll
        for (int b = 0; b < 16; b++) cs += __ldg(psprev + b * 16 + tk);
        float acc = 0.f;
        const float4* g4 = (const float4*)(G + (size_t)row * 256);
#pragma unroll 8
        for (int n4 = 0; n4 < 64; n4++) {
            float4 gv = __ldg(g4 + n4);
            acc = fmaf(gv.x, __ldg(rprev + (n4 * 4 + 0) * 16 + tk), acc);
            acc = fmaf(gv.y, __ldg(rprev + (n4 * 4 + 1) * 16 + tk), acc);
            acc = fmaf(gv.z, __ldg(rprev + (n4 * 4 + 2) * 16 + tk), acc);
            acc = fmaf(gv.w, __ldg(rprev + (n4 * 4 + 3) * 16 + tk), acc);
        }
        L = CT * acc / cs;
    }
    float mx = L;
#pragma unroll
    for (int d = 8; d >= 1; d >>= 1) mx = fmaxf(mx, __shfl_xor_sync(0xffffffffu, mx, d));
    float e = expf(L - mx);
    float s = e;
#pragma unroll
    for (int d = 8; d >= 1; d >>= 1) s += __shfl_xor_sync(0xffffffffu, s, d);
    float r = e / s;
    rout[row * 16 + tk] = r;

    ps[rloc][tk] = r;
    __syncthreads();
    if (tid < 16) {
        float ss = 0.f;
#pragma unroll
        for (int rr = 0; rr < 16; rr++) ss += ps[rr][tid];
        psout[blockIdx.x * 16 + tid] = ss;
    }
}

// ============================ host ============================
extern "C" void kernel_launch(void* const* d_in, const int* in_sizes, int n_in,
                              void* d_out, int out_size)
{
    const float* x   = (const float*)d_in[0];
    const float* w1  = (const float*)d_in[1];
    const float* b1  = (const float*)d_in[2];
    const float* g1  = (const float*)d_in[3];
    const float* be1 = (const float*)d_in[4];
    const float* m1  = (const float*)d_in[5];
    const float* v1  = (const float*)d_in[6];
    const float* w2  = (const float*)d_in[7];
    const float* b2  = (const float*)d_in[8];
    const float* g2  = (const float*)d_in[9];
    const float* be2 = (const float*)d_in[10];
    const float* m2  = (const float*)d_in[11];
    const float* v2  = (const float*)d_in[12];
    const float* w3  = (const float*)d_in[13];
    const float* b3  = (const float*)d_in[14];
    const float* g3  = (const float*)d_in[15];
    const float* be3 = (const float*)d_in[16];
    const float* m3  = (const float*)d_in[17];
    const float* v3  = (const float*)d_in[18];
    const float* mu0 = (const float*)d_in[19];

    float *data, *G, *D0, *Ra, *Rb, *PSa, *PSb;
    __half *h1, *h2, *B1, *B2, *B3;
    cudaGetSymbolAddress((void**)&h1, g_h1);
    cudaGetSymbolAddress((void**)&h2, g_h2);
    cudaGetSymbolAddress((void**)&data, g_data);
    cudaGetSymbolAddress((void**)&G, g_G);
    cudaGetSymbolAddress((void**)&D0, g_D0);
    cudaGetSymbolAddress((void**)&Ra, g_Ra);
    cudaGetSymbolAddress((void**)&Rb, g_Rb);
    cudaGetSymbolAddress((void**)&PSa, g_PSa);
    cudaGetSymbolAddress((void**)&PSb, g_PSb);
    cudaGetSymbolAddress((void**)&B1, g_B1);
    cudaGetSymbolAddress((void**)&B2, g_B2);
    cudaGetSymbolAddress((void**)&B3, g_B3);

    const int smem_c1 = 66048;
    const int smem_g2 = 2 * (128 * 144 + 128 * 144);   // 73728 (stage 66048 fits)
    const int smem_g3 = 2 * (128 * 144 + 64 * 144);    // 55296 (stage 33280 fits)
    cudaFuncSetAttribute(conv1_kernel, cudaFuncAttributeMaxDynamicSharedMemorySize, smem_c1);
    cudaFuncSetAttribute(gemm_kernel<2>, cudaFuncAttributeMaxDynamicSharedMemorySize, smem_g2);
    cudaFuncSetAttribute(gemm_kernel<3>, cudaFuncAttributeMaxDynamicSharedMemorySize, smem_g3);

    prep_w1<<<1, 128>>>(w1, B1);
    conv1_kernel<<<2048, 256, smem_c1>>>(x, B1, b1, g1, be1, m1, v1, h1);
    prep_w2<<<256, 256>>>(w2, B2);
    gemm_kernel<2><<<dim3(512, 2), 256, smem_g2>>>(h1, B2, b2, g2, be2, m2, v2, h2);
    prep_w3<<<64, 256>>>(w3, B3);
    gemm_kernel<3><<<dim3(128, 1), 256, smem_g3>>>(h2, B3, b3, g3, be3, m3, v3, data);

    normalize_kernel<<<256, 256>>>(data);
    gram_kernel<<<dim3(16, 16), 256>>>(data, G);
    dist0_kernel<<<256, 256>>>(data, mu0, D0);

    float* rin = Ra;  float* rout = Rb;
    float* pin = PSa; float* pout = PSb;
    for (int it = 0; it < 12; it++) {
        float* rdst = (it == 11) ? (float*)d_out : rout;
        kiter_kernel<<<16, 256>>>(G, D0, rin, pin, rdst, pout, it);
        float* t = rin; rin = rout; rout = t;
        t = pin; pin = pout; pout = t;
    }
}

// round 15
// speedup vs baseline: 1.3641x; 1.0069x over previous
#include <cuda_runtime.h>
#include <cuda_fp16.h>
#include <math.h>
#include <stdint.h>

#define BN_EPS 1e-3f
#define SLOPE  0.1f
#define CT     30.0f

// ============================ scratch globals ============================
__device__ __half g_h1[256 * 32 * 32 * 128];  // conv1 out NHWC fp16
__device__ __half g_h2[256 * 16 * 16 * 256];  // conv2 out NHWC fp16
__device__ float g_data[256 * 4096];
__device__ float g_G[256 * 256];
__device__ float g_D0[256 * 16];
__device__ float g_Ra[256 * 16];
__device__ float g_Rb[256 * 16];
__device__ float g_PSa[16 * 16];
__device__ float g_PSb[16 * 16];
__device__ __half g_B1[128 * 64];
__device__ __half g_B2[256 * 1152];           // k = kk*128 + ic
__device__ __half g_B3[64 * 2304];            // k = kk*256 + ic

__device__ __forceinline__ uint32_t smem_u32(const void* p) {
    uint32_t a;
    asm("{ .reg .u64 t; cvta.to.shared.u64 t, %1; cvt.u32.u64 %0, t; }" : "=r"(a) : "l"(p));
    return a;
}
__device__ __forceinline__ void cp_async16(uint32_t dst, const void* src) {
    asm volatile("cp.async.cg.shared.global [%0], [%1], 16;" :: "r"(dst), "l"(src));
}
__device__ __forceinline__ void cp_async16z(uint32_t dst, const void* src, int szbytes) {
    asm volatile("cp.async.cg.shared.global [%0], [%1], 16, %2;"
                 :: "r"(dst), "l"(src), "r"(szbytes));
}
__device__ __forceinline__ void ldsm_x4(uint32_t* f, uint32_t addr) {
    asm volatile("ldmatrix.sync.aligned.m8n8.x4.shared.b16 {%0,%1,%2,%3}, [%4];"
                 : "=r"(f[0]), "=r"(f[1]), "=r"(f[2]), "=r"(f[3]) : "r"(addr));
}
__device__ __forceinline__ void mma_f16(float* d, const uint32_t* a, const uint32_t* b) {
    asm volatile(
        "mma.sync.aligned.m16n8k16.row.col.f32.f16.f16.f32 "
        "{%0,%1,%2,%3}, {%4,%5,%6,%7}, {%8,%9}, {%0,%1,%2,%3};"
        : "+f"(d[0]), "+f"(d[1]), "+f"(d[2]), "+f"(d[3])
        : "r"(a[0]), "r"(a[1]), "r"(a[2]), "r"(a[3]), "r"(b[0]), "r"(b[1]));
}

// ============================ weight prep ============================
__global__ __launch_bounds__(128) void prep_w1(const float* __restrict__ w, __half* __restrict__ o)
{
    int oc = threadIdx.x;
    __half* row = o + oc * 64;
#pragma unroll
    for (int j = 0; j < 64; j++) row[j] = __ushort_as_half((unsigned short)0);
#pragma unroll
    for (int j = 0; j < 27; j++) row[j] = __float2half_rn(w[oc * 27 + j]);
}
__global__ __launch_bounds__(256) void prep_w2(const float* __restrict__ w, __half* __restrict__ o)
{
    int oc = blockIdx.x;
    for (int k = threadIdx.x; k < 1152; k += 256) {
        int kk = k >> 7, ic = k & 127;
        o[oc * 1152 + k] = __float2half_rn(w[oc * 1152 + ic * 9 + kk]);
    }
}
__global__ __launch_bounds__(256) void prep_w3(const float* __restrict__ w, __half* __restrict__ o)
{
    int oc = blockIdx.x;
    for (int k = threadIdx.x; k < 2304; k += 256) {
        int kk = k >> 8, ic = k & 255;
        o[oc * 2304 + k] = __float2half_rn(w[oc * 2304 + ic * 9 + kk]);
    }
}

// ============================ conv1: fully fused (x fp32 -> h1 NHWC fp16) ============================
__global__ __launch_bounds__(256)
void conv1_kernel(const float* __restrict__ x, const __half* __restrict__ Bw,
                  const float* __restrict__ bias, const float* __restrict__ g,
                  const float* __restrict__ beta, const float* __restrict__ m,
                  const float* __restrict__ v, __half* __restrict__ out)
{
    extern __shared__ __align__(16) char smem[];
    __shared__ float scs[128], shs[128];
    float* in_s = (float*)smem;                 // 1920 floats
    const int A_OFF = 7680, B_OFF = 26112;

    int tid = threadIdx.x, wid = tid >> 5, lane = tid & 31;
    int wm = wid & 3, wn = wid >> 2;
    int rowbase = blockIdx.x * 128;
    int img = rowbase >> 10, p0 = rowbase & 1023;
    int oh0 = p0 >> 5;
    int ihb0 = 2 * oh0 - 1;

    if (tid < 128) {
        float sc = g[tid] / sqrtf(v[tid] + BN_EPS);
        scs[tid] = sc;
        shs[tid] = beta[tid] - m[tid] * sc + bias[tid] * sc;
    }

    uint32_t sb = smem_u32(smem);

#pragma unroll
    for (int i = 0; i < 4; i++) {
        int gi = tid + 256 * i; int rr = gi >> 3, gc = gi & 7;
        cp_async16(sb + B_OFF + rr * 144 + gc * 16, (const char*)Bw + (rr * 64 + gc * 8) * 2);
    }
    asm volatile("cp.async.commit_group;");

    const float* xim = x + (size_t)img * 12288;
    for (int i = tid; i < 1920; i += 256) {
        int ic = i / 640, rem = i - ic * 640;
        int r = rem >> 6, cidx = rem & 63;
        int gih = ihb0 + r;
        in_s[i] = (gih >= 0 && gih < 64) ? xim[ic * 4096 + (gih << 6) + cidx] : 0.f;
    }
    __syncthreads();

    {
        int row = tid & 127, seg = tid >> 7;
        int p = p0 + row;
        int oh = p >> 5, ow = p & 31;
        int ohl = oh - oh0;
        uint32_t* arow = (uint32_t*)(smem + A_OFF + row * 144);
        if (seg == 0) {
            uint32_t t[7];
#pragma unroll
            for (int i = 0; i < 7; i++) t[i] = 0;
#pragma unroll
            for (int j = 0; j < 14; j++) {
                int ic = j / 9, kk = j % 9, kh = kk / 3, kw = kk % 3;
                int lih = 2 * ohl + kh;
                int iw = 2 * ow - 1 + kw;
                float val = ((unsigned)iw < 64u) ? in_s[ic * 640 + (lih << 6) + iw] : 0.f;
                t[j >> 1] |= (uint32_t)__half_as_ushort(__float2half_rn(val)) << ((j & 1) * 16);
            }
#pragma unroll
            for (int i = 0; i < 7; i++) arow[i] = t[i];
        } else {
            uint32_t t[7];
#pragma unroll
            for (int i = 0; i < 7; i++) t[i] = 0;
#pragma unroll
            for (int j = 14; j < 27; j++) {
                int ic = j / 9, kk = j % 9, kh = kk / 3, kw = kk % 3;
                int lih = 2 * ohl + kh;
                int iw = 2 * ow - 1 + kw;
                float val = ((unsigned)iw < 64u) ? in_s[ic * 640 + (lih << 6) + iw] : 0.f;
                t[(j >> 1) - 7] |= (uint32_t)__half_as_ushort(__float2half_rn(val)) << ((j & 1) * 16);
            }
#pragma unroll
            for (int i = 0; i < 7; i++) arow[7 + i] = t[i];
#pragma unroll
            for (int i = 14; i < 32; i++) arow[i] = 0;
        }
    }
    asm volatile("cp.async.wait_group 0;");
    __syncthreads();

    float acc[2][8][4];
#pragma unroll
    for (int i = 0; i < 2; i++)
#pragma unroll
        for (int j = 0; j < 8; j++)
#pragma unroll
            for (int q = 0; q < 4; q++) acc[i][j][q] = 0.f;

    uint32_t ab = sb + A_OFF, bb = sb + B_OFF;
#pragma unroll
    for (int ks = 0; ks < 4; ks++) {
        uint32_t af[2][4];
#pragma unroll
        for (int mt = 0; mt < 2; mt++) {
            uint32_t addr = ab + (wm * 32 + mt * 16 + (lane & 15)) * 144
                            + ks * 32 + ((lane >> 4) << 4);
            ldsm_x4(af[mt], addr);
        }
#pragma unroll
        for (int nt2 = 0; nt2 < 4; nt2++) {
            uint32_t bf[4];
            uint32_t addr = bb + (wn * 64 + nt2 * 16 + (lane & 7) + (((lane >> 4) & 1) << 3)) * 144
                            + ks * 32 + (((lane >> 3) & 1) << 4);
            ldsm_x4(bf, addr);
#pragma unroll
            for (int mt = 0; mt < 2; mt++) {
                mma_f16(acc[mt][2 * nt2],     af[mt], bf);
                mma_f16(acc[mt][2 * nt2 + 1], af[mt], bf + 2);
            }
        }
    }
    __syncthreads();

    float* stage = (float*)smem;
#pragma unroll
    for (int mt = 0; mt < 2; mt++)
#pragma unroll
        for (int nt = 0; nt < 8; nt++) {
            int r0 = wm * 32 + mt * 16 + (lane >> 2);
            int c0 = wn * 64 + nt * 8 + 2 * (lane & 3);
            stage[r0 * 129 + c0]           = acc[mt][nt][0];
            stage[r0 * 129 + c0 + 1]       = acc[mt][nt][1];
            stage[(r0 + 8) * 129 + c0]     = acc[mt][nt][2];
            stage[(r0 + 8) * 129 + c0 + 1] = acc[mt][nt][3];
        }
    __syncthreads();

    __half2* o2 = (__half2*)out;
#pragma unroll
    for (int rblk = 0; rblk < 16; rblk++) {
        int r = wid * 16 + rblk;
        size_t base2 = ((size_t)(rowbase + r) * 128) >> 1;
#pragma unroll
        for (int cc = lane; cc < 64; cc += 32) {
            float y0 = stage[r * 129 + 2 * cc] * scs[2 * cc] + shs[2 * cc];
            float y1 = stage[r * 129 + 2 * cc + 1] * scs[2 * cc + 1] + shs[2 * cc + 1];
            y0 = y0 > 0.f ? y0 : SLOPE * y0;
            y1 = y1 > 0.f ? y1 : SLOPE * y1;
            o2[base2 + cc] = __floats2half2_rn(y0, y1);
        }
    }
}

// ============================ HMMA GEMM (fp16, fused gather; CONV 2/3) ============================
// CONV2: BM=128, BN=128, grid (512,2). CONV3: BM=64, BN=64, grid (256,1).
// Hoisted gather addressing + single __syncthreads per chunk.
template<int CONV>
__global__ __launch_bounds__(256, 2)
void gemm_kernel(const __half* __restrict__ A, const __half* __restrict__ Bw,
                 const float* __restrict__ bias, const float* __restrict__ g,
                 const float* __restrict__ beta, const float* __restrict__ m,
                 const float* __restrict__ v, void* __restrict__ out_v)
{
    constexpr int KS = (CONV == 2) ? 1152 : 2304;
    constexpr int NC = KS / 64;
    constexpr int BM = (CONV == 2) ? 128 : 64;
    constexpr int BN = (CONV == 2) ? 128 : 64;
    constexpr int WM_CNT = BM / 32;          // 4 or 2
    constexpr int WN_CNT = 8 / WM_CNT;       // 2 or 4
    constexpr int WN = BN / WN_CNT;          // 64 or 16
    constexpr int NT = WN / 8;               // 8 or 2
    constexpr int ABUF = BM * 144;
    constexpr int BBUF = BN * 144;
    constexpr int AGI = BM / 32;             // A cp.async per thread
    constexpr int BGI = BN / 32;
    constexpr int P = BN + 1;
    constexpr int KWSTRIDE = (CONV == 2) ? 128 : 256;   // elements per iw step

    extern __shared__ __align__(16) char smem[];
    __shared__ float scs[BN], shs[BN];

    int tid = threadIdx.x, wid = tid >> 5, lane = tid & 31;
    int wm = wid % WM_CNT, wn = wid / WM_CNT;
    int rowbase = blockIdx.x * BM;
    int nb0 = blockIdx.y * BN;

    if (tid < BN) {
        int gcol = nb0 + tid;
        float sc = g[gcol] / sqrtf(v[gcol] + BN_EPS);
        scs[tid] = sc;
        shs[tid] = beta[gcol] - m[gcol] * sc + bias[gcol] * sc;
    }

    uint32_t sb = smem_u32(smem);

    // ---- hoisted per-thread gather state ----
    int gc = tid & 7;
    long long abase[AGI];
    uint32_t amask[AGI];     // bits [2:0] kh-valid, bits [6:4] kw-valid
    uint32_t adoff[AGI];
    const char* bbase[BGI];
    uint32_t bdoff[BGI];
#pragma unroll
    for (int i = 0; i < AGI; i++) {
        int rr = (tid >> 3) + 32 * i;
        adoff[i] = rr * 144 + gc * 16;
        if (CONV == 2) {
            int img0 = rowbase >> 8, p0 = rowbase & 255;
            int p = p0 + rr;
            int oh = p >> 4, ow = p & 15;
            abase[i] = ((((long long)img0 * 32 + (2 * oh - 1)) * 32) + (2 * ow - 1)) * 128 + gc * 8;
            amask[i] = ((oh > 0 ? 7u : 6u)) | ((ow > 0 ? 7u : 6u) << 4);
        } else {
            int grow = rowbase + rr;
            int img = grow >> 6, p = grow & 63;
            int oh = p >> 3, ow = p & 7;
            abase[i] = ((((long long)img * 16 + (2 * oh - 1)) * 16) + (2 * ow - 1)) * 256 + gc * 8;
            amask[i] = ((oh > 0 ? 7u : 6u)) | ((ow > 0 ? 7u : 6u) << 4);
        }
    }
#pragma unroll
    for (int i = 0; i < BGI; i++) {
        int rr = (tid >> 3) + 32 * i;
        bdoff[i] = rr * 144 + gc * 16;
        bbase[i] = (const char*)Bw + (((size_t)(nb0 + rr)) * KS + gc * 8) * 2;
    }

    float acc[2][NT][4];
#pragma unroll
    for (int i = 0; i < 2; i++)
#pragma unroll
        for (int j = 0; j < NT; j++)
#pragma unroll
            for (int q = 0; q < 4; q++) acc[i][j][q] = 0.f;

    auto issue_copy = [&](int c) {
        int buf = c & 1;
        uint32_t ab = sb + buf * (ABUF + BBUF);
        uint32_t bb = ab + ABUF;
        int kk = (CONV == 2) ? (c >> 1) : (c >> 2);
        int icg = (CONV == 2) ? (c & 1) : (c & 3);
        int kh = kk / 3, kw = kk - 3 * kh;
        long long delta = (long long)kh * 4096 + kw * KWSTRIDE + icg * 64;
#pragma unroll
        for (int i = 0; i < AGI; i++) {
            uint32_t ok = (amask[i] >> kh) & (amask[i] >> (4 + kw)) & 1u;
            const char* src = ok ? (const char*)A + (abase[i] + delta) * 2 : (const char*)A;
            cp_async16z(ab + adoff[i], src, ok ? 16 : 0);
        }
#pragma unroll
        for (int i = 0; i < BGI; i++)
            cp_async16(bb + bdoff[i], bbase[i] + c * 128);
        asm volatile("cp.async.commit_group;");
    };

    issue_copy(0);
    for (int c = 0; c < NC; c++) {
        asm volatile("cp.async.wait_group 0;");
        __syncthreads();
        if (c + 1 < NC) issue_copy(c + 1);

        int buf = c & 1;
        uint32_t ab = sb + buf * (ABUF + BBUF);
        uint32_t bb = ab + ABUF;
#pragma unroll
        for (int ks = 0; ks < 4; ks++) {
            uint32_t af[2][4];
#pragma unroll
            for (int mt = 0; mt < 2; mt++) {
                uint32_t addr = ab + (wm * 32 + mt * 16 + (lane & 15)) * 144
                                + ks * 32 + ((lane >> 4) << 4);
                ldsm_x4(af[mt], addr);
            }
#pragma unroll
            for (int nt2 = 0; nt2 < NT / 2; nt2++) {
                uint32_t bf[4];
                uint32_t addr = bb + (wn * WN + nt2 * 16 + (lane & 7) + (((lane >> 4) & 1) << 3)) * 144
                                + ks * 32 + (((lane >> 3) & 1) << 4);
                ldsm_x4(bf, addr);
#pragma unroll
                for (int mt = 0; mt < 2; mt++) {
                    mma_f16(acc[mt][2 * nt2],     af[mt], bf);
                    mma_f16(acc[mt][2 * nt2 + 1], af[mt], bf + 2);
                }
            }
        }
    }
    __syncthreads();

    float* stage = (float*)smem;
#pragma unroll
    for (int mt = 0; mt < 2; mt++)
#pragma unroll
        for (int nt = 0; nt < NT; nt++) {
            int r0 = wm * 32 + mt * 16 + (lane >> 2);
            int c0 = wn * WN + nt * 8 + 2 * (lane & 3);
            stage[r0 * P + c0]           = acc[mt][nt][0];
            stage[r0 * P + c0 + 1]       = acc[mt][nt][1];
            stage[(r0 + 8) * P + c0]     = acc[mt][nt][2];
            stage[(r0 + 8) * P + c0 + 1] = acc[mt][nt][3];
        }
    __syncthreads();

    if (CONV == 3) {
#pragma unroll
        for (int j = 0; j < BN / 8; j++) {
            int colL = wid * (BN / 8) + j;
            float sc = scs[colL], sh = shs[colL];
#pragma unroll
            for (int it = 0; it < BM / 32; it++) {
                int r = it * 32 + lane;
                float y = stage[r * P + colL] * sc + sh;
                y = y > 0.f ? y : SLOPE * y;
                int grow = rowbase + r;
                int img = grow >> 6, p = grow & 63;
                ((float*)out_v)[(size_t)img * 4096 + colL * 64 + p] = y;
            }
        }
    } else {
        __half2* o2 = (__half2*)out_v;
#pragma unroll
        for (int rblk = 0; rblk < BM / 8; rblk++) {
            int r = wid * (BM / 8) + rblk;
            size_t base2 = ((size_t)(rowbase + r) * 256 + nb0) >> 1;
#pragma unroll
            for (int cc = lane; cc < BN / 2; cc += 32) {
                float y0 = stage[r * P + 2 * cc] * scs[2 * cc] + shs[2 * cc];
                float y1 = stage[r * P + 2 * cc + 1] * scs[2 * cc + 1] + shs[2 * cc + 1];
                y0 = y0 > 0.f ? y0 : SLOPE * y0;
                y1 = y1 > 0.f ? y1 : SLOPE * y1;
                o2[base2 + cc] = __floats2half2_rn(y0, y1);
            }
        }
    }
}

// ============================ k-means ============================
__global__ __launch_bounds__(256) void normalize_kernel(float* __restrict__ data)
{
    int row = blockIdx.x, tid = threadIdx.x;
    float* dr = data + row * 4096;
    float vals[16];
    float s = 0.f;
#pragma unroll
    for (int i = 0; i < 16; i++) { vals[i] = dr[tid + i * 256]; s = fmaf(vals[i], vals[i], s); }
    __shared__ float sm[9];
    int lane = tid & 31, warp = tid >> 5;
#pragma unroll
    for (int off = 16; off > 0; off >>= 1) s += __shfl_down_sync(0xffffffffu, s, off);
    if (lane == 0) sm[warp] = s;
    __syncthreads();
    if (tid == 0) {
        float t = 0.f;
        for (int w = 0; w < 8; w++) t += sm[w];
        sm[8] = 1.f / sqrtf(t);
    }
    __syncthreads();
    float inv = sm[8];
#pragma unroll
    for (int i = 0; i < 16; i++) dr[tid + i * 256] = vals[i] * inv;
}

__global__ __launch_bounds__(256) void gram_kernel(const float* __restrict__ data, float* __restrict__ G)
{
    __shared__ float at[16][129];
    __shared__ float bt[16][129];
    int tid = threadIdx.x;
    int ty = tid >> 4, tx = tid & 15;
    int r0 = blockIdx.y * 16, c0 = blockIdx.x * 16;
    float acc = 0.f;
    for (int kc = 0; kc < 4096; kc += 128) {
        __syncthreads();
        for (int i = tid; i < 2048; i += 256) {
            int rr = i >> 7, cc = i & 127;
            at[rr][cc] = data[(size_t)(r0 + rr) * 4096 + kc + cc];
            bt[rr][cc] = data[(size_t)(c0 + rr) * 4096 + kc + cc];
        }
        __syncthreads();
#pragma unroll 16
        for (int k = 0; k < 128; k++) acc = fmaf(at[ty][k], bt[tx][k], acc);
    }
    G[(r0 + ty) * 256 + c0 + tx] = acc;
}

__global__ __launch_bounds__(256) void dist0_kernel(
    const float* __restrict__ data, const float* __restrict__ mu, float* __restrict__ dout)
{
    int row = blockIdx.x, tid = threadIdx.x;
    const float* dr = data + row * 4096;
    float acc[16];
#pragma unroll
    for (int k = 0; k < 16; k++) acc[k] = 0.f;
#pragma unroll 4
    for (int i = 0; i < 16; i++) {
        int j = tid + i * 256;
        float dj = __ldg(dr + j);
#pragma unroll
        for (int k = 0; k < 16; k++) acc[k] = fmaf(dj, __ldg(mu + k * 4096 + j), acc[k]);
    }
    __shared__ float wsum[8][16];
    int lane = tid & 31, warp = tid >> 5;
#pragma unroll
    for (int k = 0; k < 16; k++) {
        float vv = acc[k];
#pragma unroll
        for (int off = 16; off > 0; off >>= 1) vv += __shfl_down_sync(0xffffffffu, vv, off);
        if (lane == 0) wsum[warp][k] = vv;
    }
    __syncthreads();
    if (tid < 16) {
        float s = 0.f;
#pragma unroll
        for (int w = 0; w < 8; w++) s += wsum[w][tid];
        dout[row * 16 + tid] = s;
    }
}

__global__ __launch_bounds__(256) void kiter_kernel(
    const float* __restrict__ G, const float* __restrict__ D0,
    const float* __restrict__ rprev, const float* __restrict__ psprev,
    float* __restrict__ rout, float* __restrict__ psout, int it)
{
    __shared__ float ps[16][16];
    int tid = threadIdx.x;
    int rloc = tid >> 4, tk = tid & 15;
    int row = blockIdx.x * 16 + rloc;

    float L;
    if (it == 0) {
        L = CT * __ldg(D0 + row * 16 + tk);
    } else {
        float cs = 0.f;
#pragma unroll
        for (int b = 0; b < 16; b++) cs += __ldg(psprev + b * 16 + tk);
        float acc = 0.f;
        const float4* g4 = (const float4*)(G + (size_t)row * 256);
#pragma unroll 8
        for (int n4 = 0; n4 < 64; n4++) {
            float4 gv = __ldg(g4 + n4);
            acc = fmaf(gv.x, __ldg(rprev + (n4 * 4 + 0) * 16 + tk), acc);
            acc = fmaf(gv.y, __ldg(rprev + (n4 * 4 + 1) * 16 + tk), acc);
            acc = fmaf(gv.z, __ldg(rprev + (n4 * 4 + 2) * 16 + tk), acc);
            acc = fmaf(gv.w, __ldg(rprev + (n4 * 4 + 3) * 16 + tk), acc);
        }
        L = CT * acc / cs;
    }
    float mx = L;
#pragma unroll
    for (int d = 8; d >= 1; d >>= 1) mx = fmaxf(mx, __shfl_xor_sync(0xffffffffu, mx, d));
    float e = expf(L - mx);
    float s = e;
#pragma unroll
    for (int d = 8; d >= 1; d >>= 1) s += __shfl_xor_sync(0xffffffffu, s, d);
    float r = e / s;
    rout[row * 16 + tk] = r;

    ps[rloc][tk] = r;
    __syncthreads();
    if (tid < 16) {
        float ss = 0.f;
#pragma unroll
        for (int rr = 0; rr < 16; rr++) ss += ps[rr][tid];
        psout[blockIdx.x * 16 + tid] = ss;
    }
}

// ============================ host ============================
extern "C" void kernel_launch(void* const* d_in, const int* in_sizes, int n_in,
                              void* d_out, int out_size)
{
    const float* x   = (const float*)d_in[0];
    const float* w1  = (const float*)d_in[1];
    const float* b1  = (const float*)d_in[2];
    const float* g1  = (const float*)d_in[3];
    const float* be1 = (const float*)d_in[4];
    const float* m1  = (const float*)d_in[5];
    const float* v1  = (const float*)d_in[6];
    const float* w2  = (const float*)d_in[7];
    const float* b2  = (const float*)d_in[8];
    const float* g2  = (const float*)d_in[9];
    const float* be2 = (const float*)d_in[10];
    const float* m2  = (const float*)d_in[11];
    const float* v2  = (const float*)d_in[12];
    const float* w3  = (const float*)d_in[13];
    const float* b3  = (const float*)d_in[14];
    const float* g3  = (const float*)d_in[15];
    const float* be3 = (const float*)d_in[16];
    const float* m3  = (const float*)d_in[17];
    const float* v3  = (const float*)d_in[18];
    const float* mu0 = (const float*)d_in[19];

    float *data, *G, *D0, *Ra, *Rb, *PSa, *PSb;
    __half *h1, *h2, *B1, *B2, *B3;
    cudaGetSymbolAddress((void**)&h1, g_h1);
    cudaGetSymbolAddress((void**)&h2, g_h2);
    cudaGetSymbolAddress((void**)&data, g_data);
    cudaGetSymbolAddress((void**)&G, g_G);
    cudaGetSymbolAddress((void**)&D0, g_D0);
    cudaGetSymbolAddress((void**)&Ra, g_Ra);
    cudaGetSymbolAddress((void**)&Rb, g_Rb);
    cudaGetSymbolAddress((void**)&PSa, g_PSa);
    cudaGetSymbolAddress((void**)&PSb, g_PSb);
    cudaGetSymbolAddress((void**)&B1, g_B1);
    cudaGetSymbolAddress((void**)&B2, g_B2);
    cudaGetSymbolAddress((void**)&B3, g_B3);

    const int smem_c1 = 66048;
    const int smem_g2 = 2 * (128 * 144 + 128 * 144);   // 73728 (stage 66048 fits)
    const int smem_g3 = 2 * (64 * 144 + 64 * 144);     // 36864 (stage 16640 fits)
    cudaFuncSetAttribute(conv1_kernel, cudaFuncAttributeMaxDynamicSharedMemorySize, smem_c1);
    cudaFuncSetAttribute(gemm_kernel<2>, cudaFuncAttributeMaxDynamicSharedMemorySize, smem_g2);
    cudaFuncSetAttribute(gemm_kernel<3>, cudaFuncAttributeMaxDynamicSharedMemorySize, smem_g3);

    prep_w1<<<1, 128>>>(w1, B1);
    conv1_kernel<<<2048, 256, smem_c1>>>(x, B1, b1, g1, be1, m1, v1, h1);
    prep_w2<<<256, 256>>>(w2, B2);
    gemm_kernel<2><<<dim3(512, 2), 256, smem_g2>>>(h1, B2, b2, g2, be2, m2, v2, h2);
    prep_w3<<<64, 256>>>(w3, B3);
    gemm_kernel<3><<<dim3(256, 1), 256, smem_g3>>>(h2, B3, b3, g3, be3, m3, v3, data);

    normalize_kernel<<<256, 256>>>(data);
    gram_kernel<<<dim3(16, 16), 256>>>(data, G);
    dist0_kernel<<<256, 256>>>(data, mu0, D0);

    float* rin = Ra;  float* rout = Rb;
    float* pin = PSa; float* pout = PSb;
    for (int it = 0; it < 12; it++) {
        float* rdst = (it == 11) ? (float*)d_out : rout;
        kiter_kernel<<<16, 256>>>(G, D0, rin, pin, rdst, pout, it);
        float* t = rin; rin = rout; rout = t;
        t = pin; pin = pout; pout = t;
    }
}

// round 16
// speedup vs baseline: 1.3767x; 1.0092x over previous
#include <cuda_runtime.h>
#include <cuda_fp16.h>
#include <math.h>
#include <stdint.h>

#define BN_EPS 1e-3f
#define SLOPE  0.1f
#define CT     30.0f

// ============================ scratch globals ============================
__device__ __half g_h1[256 * 32 * 32 * 128];  // conv1 out NHWC fp16
__device__ __half g_h2[256 * 16 * 16 * 256];  // conv2 out NHWC fp16
__device__ float g_data[256 * 4096];
__device__ float g_G[256 * 256];
__device__ float g_D0[256 * 16];
__device__ float g_Ra[256 * 16];
__device__ float g_Rb[256 * 16];
__device__ float g_PSa[16 * 16];
__device__ float g_PSb[16 * 16];
__device__ __half g_B1[128 * 64];
__device__ __half g_B2[256 * 1152];           // k = kk*128 + ic
__device__ __half g_B3[64 * 2304];            // k = kk*256 + ic

__device__ __forceinline__ uint32_t smem_u32(const void* p) {
    uint32_t a;
    asm("{ .reg .u64 t; cvta.to.shared.u64 t, %1; cvt.u32.u64 %0, t; }" : "=r"(a) : "l"(p));
    return a;
}
__device__ __forceinline__ void cp_async16(uint32_t dst, const void* src) {
    asm volatile("cp.async.cg.shared.global [%0], [%1], 16;" :: "r"(dst), "l"(src));
}
__device__ __forceinline__ void cp_async16z(uint32_t dst, const void* src, int szbytes) {
    asm volatile("cp.async.cg.shared.global [%0], [%1], 16, %2;"
                 :: "r"(dst), "l"(src), "r"(szbytes));
}
__device__ __forceinline__ void ldsm_x4(uint32_t* f, uint32_t addr) {
    asm volatile("ldmatrix.sync.aligned.m8n8.x4.shared.b16 {%0,%1,%2,%3}, [%4];"
                 : "=r"(f[0]), "=r"(f[1]), "=r"(f[2]), "=r"(f[3]) : "r"(addr));
}
__device__ __forceinline__ void mma_f16(float* d, const uint32_t* a, const uint32_t* b) {
    asm volatile(
        "mma.sync.aligned.m16n8k16.row.col.f32.f16.f16.f32 "
        "{%0,%1,%2,%3}, {%4,%5,%6,%7}, {%8,%9}, {%0,%1,%2,%3};"
        : "+f"(d[0]), "+f"(d[1]), "+f"(d[2]), "+f"(d[3])
        : "r"(a[0]), "r"(a[1]), "r"(a[2]), "r"(a[3]), "r"(b[0]), "r"(b[1]));
}

// ============================ weight prep ============================
__global__ __launch_bounds__(128) void prep_w1(const float* __restrict__ w, __half* __restrict__ o)
{
    int oc = threadIdx.x;
    __half* row = o + oc * 64;
#pragma unroll
    for (int j = 0; j < 64; j++) row[j] = __ushort_as_half((unsigned short)0);
#pragma unroll
    for (int j = 0; j < 27; j++) row[j] = __float2half_rn(w[oc * 27 + j]);
}
__global__ __launch_bounds__(256) void prep_w2(const float* __restrict__ w, __half* __restrict__ o)
{
    int oc = blockIdx.x;
    for (int k = threadIdx.x; k < 1152; k += 256) {
        int kk = k >> 7, ic = k & 127;
        o[oc * 1152 + k] = __float2half_rn(w[oc * 1152 + ic * 9 + kk]);
    }
}
__global__ __launch_bounds__(256) void prep_w3(const float* __restrict__ w, __half* __restrict__ o)
{
    int oc = blockIdx.x;
    for (int k = threadIdx.x; k < 2304; k += 256) {
        int kk = k >> 8, ic = k & 255;
        o[oc * 2304 + k] = __float2half_rn(w[oc * 2304 + ic * 9 + kk]);
    }
}

// ============================ conv1: fully fused (x fp32 -> h1 NHWC fp16) ============================
__global__ __launch_bounds__(256)
void conv1_kernel(const float* __restrict__ x, const __half* __restrict__ Bw,
                  const float* __restrict__ bias, const float* __restrict__ g,
                  const float* __restrict__ beta, const float* __restrict__ m,
                  const float* __restrict__ v, __half* __restrict__ out)
{
    extern __shared__ __align__(16) char smem[];
    __shared__ float scs[128], shs[128];
    float* in_s = (float*)smem;                 // 1920 floats
    const int A_OFF = 7680, B_OFF = 26112;

    int tid = threadIdx.x, wid = tid >> 5, lane = tid & 31;
    int wm = wid & 3, wn = wid >> 2;
    int rowbase = blockIdx.x * 128;
    int img = rowbase >> 10, p0 = rowbase & 1023;
    int oh0 = p0 >> 5;
    int ihb0 = 2 * oh0 - 1;

    if (tid < 128) {
        float sc = g[tid] / sqrtf(v[tid] + BN_EPS);
        scs[tid] = sc;
        shs[tid] = beta[tid] - m[tid] * sc + bias[tid] * sc;
    }

    uint32_t sb = smem_u32(smem);

#pragma unroll
    for (int i = 0; i < 4; i++) {
        int gi = tid + 256 * i; int rr = gi >> 3, gc = gi & 7;
        cp_async16(sb + B_OFF + rr * 144 + gc * 16, (const char*)Bw + (rr * 64 + gc * 8) * 2);
    }
    asm volatile("cp.async.commit_group;");

    const float* xim = x + (size_t)img * 12288;
    for (int i = tid; i < 1920; i += 256) {
        int ic = i / 640, rem = i - ic * 640;
        int r = rem >> 6, cidx = rem & 63;
        int gih = ihb0 + r;
        in_s[i] = (gih >= 0 && gih < 64) ? xim[ic * 4096 + (gih << 6) + cidx] : 0.f;
    }
    __syncthreads();

    {
        int row = tid & 127, seg = tid >> 7;
        int p = p0 + row;
        int oh = p >> 5, ow = p & 31;
        int ohl = oh - oh0;
        uint32_t* arow = (uint32_t*)(smem + A_OFF + row * 144);
        if (seg == 0) {
            uint32_t t[7];
#pragma unroll
            for (int i = 0; i < 7; i++) t[i] = 0;
#pragma unroll
            for (int j = 0; j < 14; j++) {
                int ic = j / 9, kk = j % 9, kh = kk / 3, kw = kk % 3;
                int lih = 2 * ohl + kh;
                int iw = 2 * ow - 1 + kw;
                float val = ((unsigned)iw < 64u) ? in_s[ic * 640 + (lih << 6) + iw] : 0.f;
                t[j >> 1] |= (uint32_t)__half_as_ushort(__float2half_rn(val)) << ((j & 1) * 16);
            }
#pragma unroll
            for (int i = 0; i < 7; i++) arow[i] = t[i];
        } else {
            uint32_t t[7];
#pragma unroll
            for (int i = 0; i < 7; i++) t[i] = 0;
#pragma unroll
            for (int j = 14; j < 27; j++) {
                int ic = j / 9, kk = j % 9, kh = kk / 3, kw = kk % 3;
                int lih = 2 * ohl + kh;
                int iw = 2 * ow - 1 + kw;
                float val = ((unsigned)iw < 64u) ? in_s[ic * 640 + (lih << 6) + iw] : 0.f;
                t[(j >> 1) - 7] |= (uint32_t)__half_as_ushort(__float2half_rn(val)) << ((j & 1) * 16);
            }
#pragma unroll
            for (int i = 0; i < 7; i++) arow[7 + i] = t[i];
#pragma unroll
            for (int i = 14; i < 32; i++) arow[i] = 0;
        }
    }
    asm volatile("cp.async.wait_group 0;");
    __syncthreads();

    float acc[2][8][4];
#pragma unroll
    for (int i = 0; i < 2; i++)
#pragma unroll
        for (int j = 0; j < 8; j++)
#pragma unroll
            for (int q = 0; q < 4; q++) acc[i][j][q] = 0.f;

    uint32_t ab = sb + A_OFF, bb = sb + B_OFF;
#pragma unroll
    for (int ks = 0; ks < 4; ks++) {
        uint32_t af[2][4];
#pragma unroll
        for (int mt = 0; mt < 2; mt++) {
            uint32_t addr = ab + (wm * 32 + mt * 16 + (lane & 15)) * 144
                            + ks * 32 + ((lane >> 4) << 4);
            ldsm_x4(af[mt], addr);
        }
#pragma unroll
        for (int nt2 = 0; nt2 < 4; nt2++) {
            uint32_t bf[4];
            uint32_t addr = bb + (wn * 64 + nt2 * 16 + (lane & 7) + (((lane >> 4) & 1) << 3)) * 144
                            + ks * 32 + (((lane >> 3) & 1) << 4);
            ldsm_x4(bf, addr);
#pragma unroll
            for (int mt = 0; mt < 2; mt++) {
                mma_f16(acc[mt][2 * nt2],     af[mt], bf);
                mma_f16(acc[mt][2 * nt2 + 1], af[mt], bf + 2);
            }
        }
    }
    __syncthreads();

    float* stage = (float*)smem;
#pragma unroll
    for (int mt = 0; mt < 2; mt++)
#pragma unroll
        for (int nt = 0; nt < 8; nt++) {
            int r0 = wm * 32 + mt * 16 + (lane >> 2);
            int c0 = wn * 64 + nt * 8 + 2 * (lane & 3);
            stage[r0 * 129 + c0]           = acc[mt][nt][0];
            stage[r0 * 129 + c0 + 1]       = acc[mt][nt][1];
            stage[(r0 + 8) * 129 + c0]     = acc[mt][nt][2];
            stage[(r0 + 8) * 129 + c0 + 1] = acc[mt][nt][3];
        }
    __syncthreads();

    __half2* o2 = (__half2*)out;
#pragma unroll
    for (int rblk = 0; rblk < 16; rblk++) {
        int r = wid * 16 + rblk;
        size_t base2 = ((size_t)(rowbase + r) * 128) >> 1;
#pragma unroll
        for (int cc = lane; cc < 64; cc += 32) {
            float y0 = stage[r * 129 + 2 * cc] * scs[2 * cc] + shs[2 * cc];
            float y1 = stage[r * 129 + 2 * cc + 1] * scs[2 * cc + 1] + shs[2 * cc + 1];
            y0 = y0 > 0.f ? y0 : SLOPE * y0;
            y1 = y1 > 0.f ? y1 : SLOPE * y1;
            o2[base2 + cc] = __floats2half2_rn(y0, y1);
        }
    }
}

// ============================ HMMA GEMM (fp16, fused gather, 3-stage pipeline) ============================
// CONV2: BM=128, BN=128, grid (512,2). CONV3: BM=64, BN=64, grid (256,1).
template<int CONV>
__global__ __launch_bounds__(256, 2)
void gemm_kernel(const __half* __restrict__ A, const __half* __restrict__ Bw,
                 const float* __restrict__ bias, const float* __restrict__ g,
                 const float* __restrict__ beta, const float* __restrict__ m,
                 const float* __restrict__ v, void* __restrict__ out_v)
{
    constexpr int KS = (CONV == 2) ? 1152 : 2304;
    constexpr int NC = KS / 64;
    constexpr int BM = (CONV == 2) ? 128 : 64;
    constexpr int BN = (CONV == 2) ? 128 : 64;
    constexpr int WM_CNT = BM / 32;
    constexpr int WN_CNT = 8 / WM_CNT;
    constexpr int WN = BN / WN_CNT;
    constexpr int NT = WN / 8;
    constexpr int ABUF = BM * 144;
    constexpr int BBUF = BN * 144;
    constexpr int AGI = BM / 32;
    constexpr int BGI = BN / 32;
    constexpr int P = BN + 1;
    constexpr int KWSTRIDE = (CONV == 2) ? 128 : 256;

    extern __shared__ __align__(16) char smem[];
    __shared__ float scs[BN], shs[BN];

    int tid = threadIdx.x, wid = tid >> 5, lane = tid & 31;
    int wm = wid % WM_CNT, wn = wid / WM_CNT;
    int rowbase = blockIdx.x * BM;
    int nb0 = blockIdx.y * BN;

    if (tid < BN) {
        int gcol = nb0 + tid;
        float sc = g[gcol] / sqrtf(v[gcol] + BN_EPS);
        scs[tid] = sc;
        shs[tid] = beta[gcol] - m[gcol] * sc + bias[gcol] * sc;
    }

    uint32_t sb = smem_u32(smem);

    int gc = tid & 7;
    long long abase[AGI];
    uint32_t amask[AGI];
    uint32_t adoff[AGI];
    const char* bbase[BGI];
    uint32_t bdoff[BGI];
#pragma unroll
    for (int i = 0; i < AGI; i++) {
        int rr = (tid >> 3) + 32 * i;
        adoff[i] = rr * 144 + gc * 16;
        if (CONV == 2) {
            int img0 = rowbase >> 8, p0 = rowbase & 255;
            int p = p0 + rr;
            int oh = p >> 4, ow = p & 15;
            abase[i] = ((((long long)img0 * 32 + (2 * oh - 1)) * 32) + (2 * ow - 1)) * 128 + gc * 8;
            amask[i] = ((oh > 0 ? 7u : 6u)) | ((ow > 0 ? 7u : 6u) << 4);
        } else {
            int grow = rowbase + rr;
            int img = grow >> 6, p = grow & 63;
            int oh = p >> 3, ow = p & 7;
            abase[i] = ((((long long)img * 16 + (2 * oh - 1)) * 16) + (2 * ow - 1)) * 256 + gc * 8;
            amask[i] = ((oh > 0 ? 7u : 6u)) | ((ow > 0 ? 7u : 6u) << 4);
        }
    }
#pragma unroll
    for (int i = 0; i < BGI; i++) {
        int rr = (tid >> 3) + 32 * i;
        bdoff[i] = rr * 144 + gc * 16;
        bbase[i] = (const char*)Bw + (((size_t)(nb0 + rr)) * KS + gc * 8) * 2;
    }

    float acc[2][NT][4];
#pragma unroll
    for (int i = 0; i < 2; i++)
#pragma unroll
        for (int j = 0; j < NT; j++)
#pragma unroll
            for (int q = 0; q < 4; q++) acc[i][j][q] = 0.f;

    auto issue_copy = [&](int c) {
        int buf = c % 3;
        uint32_t ab = sb + buf * (ABUF + BBUF);
        uint32_t bb = ab + ABUF;
        int kk = (CONV == 2) ? (c >> 1) : (c >> 2);
        int icg = (CONV == 2) ? (c & 1) : (c & 3);
        int kh = kk / 3, kw = kk - 3 * kh;
        long long delta = (long long)kh * 4096 + kw * KWSTRIDE + icg * 64;
#pragma unroll
        for (int i = 0; i < AGI; i++) {
            uint32_t ok = (amask[i] >> kh) & (amask[i] >> (4 + kw)) & 1u;
            const char* src = ok ? (const char*)A + (abase[i] + delta) * 2 : (const char*)A;
            cp_async16z(ab + adoff[i], src, ok ? 16 : 0);
        }
#pragma unroll
        for (int i = 0; i < BGI; i++)
            cp_async16(bb + bdoff[i], bbase[i] + c * 128);
        asm volatile("cp.async.commit_group;");
    };

    issue_copy(0);
    issue_copy(1);
    for (int c = 0; c < NC; c++) {
        if (c + 1 < NC) asm volatile("cp.async.wait_group 1;");
        else            asm volatile("cp.async.wait_group 0;");
        __syncthreads();
        if (c + 2 < NC) issue_copy(c + 2);

        int buf = c % 3;
        uint32_t ab = sb + buf * (ABUF + BBUF);
        uint32_t bb = ab + ABUF;
#pragma unroll
        for (int ks = 0; ks < 4; ks++) {
            uint32_t af[2][4];
#pragma unroll
            for (int mt = 0; mt < 2; mt++) {
                uint32_t addr = ab + (wm * 32 + mt * 16 + (lane & 15)) * 144
                                + ks * 32 + ((lane >> 4) << 4);
                ldsm_x4(af[mt], addr);
            }
#pragma unroll
            for (int nt2 = 0; nt2 < NT / 2; nt2++) {
                uint32_t bf[4];
                uint32_t addr = bb + (wn * WN + nt2 * 16 + (lane & 7) + (((lane >> 4) & 1) << 3)) * 144
                                + ks * 32 + (((lane >> 3) & 1) << 4);
                ldsm_x4(bf, addr);
#pragma unroll
                for (int mt = 0; mt < 2; mt++) {
                    mma_f16(acc[mt][2 * nt2],     af[mt], bf);
                    mma_f16(acc[mt][2 * nt2 + 1], af[mt], bf + 2);
                }
            }
        }
    }
    __syncthreads();

    float* stage = (float*)smem;
#pragma unroll
    for (int mt = 0; mt < 2; mt++)
#pragma unroll
        for (int nt = 0; nt < NT; nt++) {
            int r0 = wm * 32 + mt * 16 + (lane >> 2);
            int c0 = wn * WN + nt * 8 + 2 * (lane & 3);
            stage[r0 * P + c0]           = acc[mt][nt][0];
            stage[r0 * P + c0 + 1]       = acc[mt][nt][1];
            stage[(r0 + 8) * P + c0]     = acc[mt][nt][2];
            stage[(r0 + 8) * P + c0 + 1] = acc[mt][nt][3];
        }
    __syncthreads();

    if (CONV == 3) {
#pragma unroll
        for (int j = 0; j < BN / 8; j++) {
            int colL = wid * (BN / 8) + j;
            float sc = scs[colL], sh = shs[colL];
#pragma unroll
            for (int it = 0; it < BM / 32; it++) {
                int r = it * 32 + lane;
                float y = stage[r * P + colL] * sc + sh;
                y = y > 0.f ? y : SLOPE * y;
                int grow = rowbase + r;
                int img = grow >> 6, p = grow & 63;
                ((float*)out_v)[(size_t)img * 4096 + colL * 64 + p] = y;
            }
        }
    } else {
        __half2* o2 = (__half2*)out_v;
#pragma unroll
        for (int rblk = 0; rblk < BM / 8; rblk++) {
            int r = wid * (BM / 8) + rblk;
            size_t base2 = ((size_t)(rowbase + r) * 256 + nb0) >> 1;
#pragma unroll
            for (int cc = lane; cc < BN / 2; cc += 32) {
                float y0 = stage[r * P + 2 * cc] * scs[2 * cc] + shs[2 * cc];
                float y1 = stage[r * P + 2 * cc + 1] * scs[2 * cc + 1] + shs[2 * cc + 1];
                y0 = y0 > 0.f ? y0 : SLOPE * y0;
                y1 = y1 > 0.f ? y1 : SLOPE * y1;
                o2[base2 + cc] = __floats2half2_rn(y0, y1);
            }
        }
    }
}

// ============================ k-means ============================
__global__ __launch_bounds__(256) void normalize_kernel(float* __restrict__ data)
{
    int row = blockIdx.x, tid = threadIdx.x;
    float* dr = data + row * 4096;
    float vals[16];
    float s = 0.f;
#pragma unroll
    for (int i = 0; i < 16; i++) { vals[i] = dr[tid + i * 256]; s = fmaf(vals[i], vals[i], s); }
    __shared__ float sm[9];
    int lane = tid & 31, warp = tid >> 5;
#pragma unroll
    for (int off = 16; off > 0; off >>= 1) s += __shfl_down_sync(0xffffffffu, s, off);
    if (lane == 0) sm[warp] = s;
    __syncthreads();
    if (tid == 0) {
        float t = 0.f;
        for (int w = 0; w < 8; w++) t += sm[w];
        sm[8] = 1.f / sqrtf(t);
    }
    __syncthreads();
    float inv = sm[8];
#pragma unroll
    for (int i = 0; i < 16; i++) dr[tid + i * 256] = vals[i] * inv;
}

__global__ __launch_bounds__(256) void gram_kernel(const float* __restrict__ data, float* __restrict__ G)
{
    __shared__ float at[16][129];
    __shared__ float bt[16][129];
    int tid = threadIdx.x;
    int ty = tid >> 4, tx = tid & 15;
    int r0 = blockIdx.y * 16, c0 = blockIdx.x * 16;
    float acc = 0.f;
    for (int kc = 0; kc < 4096; kc += 128) {
        __syncthreads();
        for (int i = tid; i < 2048; i += 256) {
            int rr = i >> 7, cc = i & 127;
            at[rr][cc] = data[(size_t)(r0 + rr) * 4096 + kc + cc];
            bt[rr][cc] = data[(size_t)(c0 + rr) * 4096 + kc + cc];
        }
        __syncthreads();
#pragma unroll 16
        for (int k = 0; k < 128; k++) acc = fmaf(at[ty][k], bt[tx][k], acc);
    }
    G[(r0 + ty) * 256 + c0 + tx] = acc;
}

__global__ __launch_bounds__(256) void dist0_kernel(
    const float* __restrict__ data, const float* __restrict__ mu, float* __restrict__ dout)
{
    int row = blockIdx.x, tid = threadIdx.x;
    const float* dr = data + row * 4096;
    float acc[16];
#pragma unroll
    for (int k = 0; k < 16; k++) acc[k] = 0.f;
#pragma unroll 4
    for (int i = 0; i < 16; i++) {
        int j = tid + i * 256;
        float dj = __ldg(dr + j);
#pragma unroll
        for (int k = 0; k < 16; k++) acc[k] = fmaf(dj, __ldg(mu + k * 4096 + j), acc[k]);
    }
    __shared__ float wsum[8][16];
    int lane = tid & 31, warp = tid >> 5;
#pragma unroll
    for (int k = 0; k < 16; k++) {
        float vv = acc[k];
#pragma unroll
        for (int off = 16; off > 0; off >>= 1) vv += __shfl_down_sync(0xffffffffu, vv, off);
        if (lane == 0) wsum[warp][k] = vv;
    }
    __syncthreads();
    if (tid < 16) {
        float s = 0.f;
#pragma unroll
        for (int w = 0; w < 8; w++) s += wsum[w][tid];
        dout[row * 16 + tid] = s;
    }
}

__global__ __launch_bounds__(256) void kiter_kernel(
    const float* __restrict__ G, const float* __restrict__ D0,
    const float* __restrict__ rprev, const float* __restrict__ psprev,
    float* __restrict__ rout, float* __restrict__ psout, int it)
{
    __shared__ float ps[16][16];
    int tid = threadIdx.x;
    int rloc = tid >> 4, tk = tid & 15;
    int row = blockIdx.x * 16 + rloc;

    float L;
    if (it == 0) {
        L = CT * __ldg(D0 + row * 16 + tk);
    } else {
        float cs = 0.f;
#pragma unroll
        for (int b = 0; b < 16; b++) cs += __ldg(psprev + b * 16 + tk);
        float acc = 0.f;
        const float4* g4 = (const float4*)(G + (size_t)row * 256);
#pragma unroll 8
        for (int n4 = 0; n4 < 64; n4++) {
            float4 gv = __ldg(g4 + n4);
            acc = fmaf(gv.x, __ldg(rprev + (n4 * 4 + 0) * 16 + tk), acc);
            acc = fmaf(gv.y, __ldg(rprev + (n4 * 4 + 1) * 16 + tk), acc);
            acc = fmaf(gv.z, __ldg(rprev + (n4 * 4 + 2) * 16 + tk), acc);
            acc = fmaf(gv.w, __ldg(rprev + (n4 * 4 + 3) * 16 + tk), acc);
        }
        L = CT * acc / cs;
    }
    float mx = L;
#pragma unroll
    for (int d = 8; d >= 1; d >>= 1) mx = fmaxf(mx, __shfl_xor_sync(0xffffffffu, mx, d));
    float e = expf(L - mx);
    float s = e;
#pragma unroll
    for (int d = 8; d >= 1; d >>= 1) s += __shfl_xor_sync(0xffffffffu, s, d);
    float r = e / s;
    rout[row * 16 + tk] = r;

    ps[rloc][tk] = r;
    __syncthreads();
    if (tid < 16) {
        float ss = 0.f;
#pragma unroll
        for (int rr = 0; rr < 16; rr++) ss += ps[rr][tid];
        psout[blockIdx.x * 16 + tid] = ss;
    }
}

// ============================ host ============================
extern "C" void kernel_launch(void* const* d_in, const int* in_sizes, int n_in,
                              void* d_out, int out_size)
{
    const float* x   = (const float*)d_in[0];
    const float* w1  = (const float*)d_in[1];
    const float* b1  = (const float*)d_in[2];
    const float* g1  = (const float*)d_in[3];
    const float* be1 = (const float*)d_in[4];
    const float* m1  = (const float*)d_in[5];
    const float* v1  = (const float*)d_in[6];
    const float* w2  = (const float*)d_in[7];
    const float* b2  = (const float*)d_in[8];
    const float* g2  = (const float*)d_in[9];
    const float* be2 = (const float*)d_in[10];
    const float* m2  = (const float*)d_in[11];
    const float* v2  = (const float*)d_in[12];
    const float* w3  = (const float*)d_in[13];
    const float* b3  = (const float*)d_in[14];
    const float* g3  = (const float*)d_in[15];
    const float* be3 = (const float*)d_in[16];
    const float* m3  = (const float*)d_in[17];
    const float* v3  = (const float*)d_in[18];
    const float* mu0 = (const float*)d_in[19];

    float *data, *G, *D0, *Ra, *Rb, *PSa, *PSb;
    __half *h1, *h2, *B1, *B2, *B3;
    cudaGetSymbolAddress((void**)&h1, g_h1);
    cudaGetSymbolAddress((void**)&h2, g_h2);
    cudaGetSymbolAddress((void**)&data, g_data);
    cudaGetSymbolAddress((void**)&G, g_G);
    cudaGetSymbolAddress((void**)&D0, g_D0);
    cudaGetSymbolAddress((void**)&Ra, g_Ra);
    cudaGetSymbolAddress((void**)&Rb, g_Rb);
    cudaGetSymbolAddress((void**)&PSa, g_PSa);
    cudaGetSymbolAddress((void**)&PSb, g_PSb);
    cudaGetSymbolAddress((void**)&B1, g_B1);
    cudaGetSymbolAddress((void**)&B2, g_B2);
    cudaGetSymbolAddress((void**)&B3, g_B3);

    const int smem_c1 = 66048;
    const int smem_g2 = 3 * (128 * 144 + 128 * 144);   // 110592 (stage 66048 fits)
    const int smem_g3 = 3 * (64 * 144 + 64 * 144);     // 55296  (stage 16640 fits)
    cudaFuncSetAttribute(conv1_kernel, cudaFuncAttributeMaxDynamicSharedMemorySize, smem_c1);
    cudaFuncSetAttribute(gemm_kernel<2>, cudaFuncAttributeMaxDynamicSharedMemorySize, smem_g2);
    cudaFuncSetAttribute(gemm_kernel<3>, cudaFuncAttributeMaxDynamicSharedMemorySize, smem_g3);

    prep_w1<<<1, 128>>>(w1, B1);
    conv1_kernel<<<2048, 256, smem_c1>>>(x, B1, b1, g1, be1, m1, v1, h1);
    prep_w2<<<256, 256>>>(w2, B2);
    gemm_kernel<2><<<dim3(512, 2), 256, smem_g2>>>(h1, B2, b2, g2, be2, m2, v2, h2);
    prep_w3<<<64, 256>>>(w3, B3);
    gemm_kernel<3><<<dim3(256, 1), 256, smem_g3>>>(h2, B3, b3, g3, be3, m3, v3, data);

    normalize_kernel<<<256, 256>>>(data);
    gram_kernel<<<dim3(16, 16), 256>>>(data, G);
    dist0_kernel<<<256, 256>>>(data, mu0, D0);

    float* rin = Ra;  float* rout = Rb;
    float* pin = PSa; float* pout = PSb;
    for (int it = 0; it < 12; it++) {
        float* rdst = (it == 11) ? (float*)d_out : rout;
        kiter_kernel<<<16, 256>>>(G, D0, rin, pin, rdst, pout, it);
        float* t = rin; rin = rout; rout = t;
        t = pin; pin = pout; pout = t;
    }
}